// round 14
// baseline (speedup 1.0000x reference)
#include <cuda_runtime.h>
#include <cuda_bf16.h>
#include <cmath>

#define B_ 32
#define N_ 16384
#define D_ 64
#define S_ 8
#define H_ 128
#define LNEPS 1e-5f
#define ATTN_EPS 1e-8f

typedef unsigned long long ull;
typedef unsigned int u32;

// ---------------- scratch (device globals; no allocations allowed) ----------
__device__ unsigned g_kh[B_ * N_ * 32];   // k_pos bf16x2 (64 MB)
__device__ unsigned g_vh[B_ * N_ * 32];   // v_pos bf16x2 (64 MB)
__device__ float g_q[B_ * S_ * D_];
__device__ float g_s[B_ * S_ * D_];
__device__ float g_part[B_ * 64 * 520];   // per-(b, partial-block) numer(512)+den(8)
__device__ unsigned g_ctr[B_];            // zero-initialized arrival counters

// ---------------- helpers ----------------------------------------------------
__device__ __forceinline__ unsigned bf2u(float a, float b) {
    __nv_bfloat162 h = __float22bfloat162_rn(make_float2(a, b));
    return *(unsigned*)&h;
}
__device__ __forceinline__ float2 u2f2(unsigned u) {
    __nv_bfloat162 h = *(__nv_bfloat162*)&u;
    return __bfloat1622float2(h);
}
__device__ __forceinline__ void ldsm_x4(u32 a[4], u32 addr) {
    asm volatile("ldmatrix.sync.aligned.m8n8.x4.shared.b16 {%0,%1,%2,%3}, [%4];"
                 : "=r"(a[0]), "=r"(a[1]), "=r"(a[2]), "=r"(a[3]) : "r"(addr));
}
__device__ __forceinline__ void ldsm_x2t(u32 b[2], u32 addr) {
    asm volatile("ldmatrix.sync.aligned.m8n8.x2.trans.shared.b16 {%0,%1}, [%2];"
                 : "=r"(b[0]), "=r"(b[1]) : "r"(addr));
}
__device__ __forceinline__ void mma_bf16(float d[4], const u32 a[4], const u32 b[2]) {
    asm volatile("mma.sync.aligned.m16n8k16.row.col.f32.bf16.bf16.f32 "
                 "{%0,%1,%2,%3},{%4,%5,%6,%7},{%8,%9},{%0,%1,%2,%3};"
                 : "+f"(d[0]), "+f"(d[1]), "+f"(d[2]), "+f"(d[3])
                 : "r"(a[0]), "r"(a[1]), "r"(a[2]), "r"(a[3]), "r"(b[0]), "r"(b[1]));
}

// ---------------------------------------------------------------------------
// Kernel 1: fused preprocessing (unchanged from R11-R13 best).
// ---------------------------------------------------------------------------
#define PRE_SMEM_BYTES 93184

__global__ __launch_bounds__(256, 2) void preprocess_kernel(
    const float* __restrict__ inp,
    const float* __restrict__ lng, const float* __restrict__ lnb,
    const float* __restrict__ Wk,  const float* __restrict__ Wv,
    const float* __restrict__ paW, const float* __restrict__ pab,
    const float* __restrict__ peg, const float* __restrict__ peb,
    const float* __restrict__ W1,  const float* __restrict__ b1,
    const float* __restrict__ W2,  const float* __restrict__ b2)
{
    extern __shared__ char smem[];
    __nv_bfloat16* sWk = (__nv_bfloat16*)(smem);
    __nv_bfloat16* sWv = (__nv_bfloat16*)(smem + 9216);
    __nv_bfloat16* sW1 = (__nv_bfloat16*)(smem + 18432);
    __nv_bfloat16* sW2 = (__nv_bfloat16*)(smem + 35840);
    __nv_bfloat16* sX  = (__nv_bfloat16*)(smem + 54272);
    float*         sTf = (float*)(smem + 63488);          // aliased with sHb
    __nv_bfloat16* sHb = (__nv_bfloat16*)(smem + 63488);
    __nv_bfloat16* sTb = (__nv_bfloat16*)(smem + 80896);
    float*         sV  = (float*)(smem + 90112);
    float*         sG  = (float*)(smem + 92672);

    u32 sb = (u32)__cvta_generic_to_shared(smem);
    const u32 sbWk = sb, sbWv = sb + 9216, sbW1 = sb + 18432, sbW2 = sb + 35840;
    const u32 sbX = sb + 54272, sbHb = sb + 63488, sbTb = sb + 80896;

    const int t = threadIdx.x, warp = t >> 5, lane = t & 31;
    const int mt = warp >> 1, ng = warp & 1;
    const int l15 = lane & 15, lh = lane >> 4, lr = lane >> 2, lc = (lane & 3) * 2;

    for (int i = t; i < 4096; i += 256) {
        int r = i >> 6, c = i & 63;
        sWk[r * 72 + c] = __float2bfloat16(Wk[i]);
        sWv[r * 72 + c] = __float2bfloat16(Wv[i]);
    }
    for (int i = t; i < 8192; i += 256) {
        int r1_ = i >> 7, c1_ = i & 127;
        sW1[r1_ * 136 + c1_] = __float2bfloat16(W1[i]);
        int r2_ = i >> 6, c2_ = i & 63;
        sW2[r2_ * 72 + c2_] = __float2bfloat16(W2[i]);
    }
    if (t < 64) {
        sV[t]       = paW[t];
        sV[64 + t]  = paW[64 + t];
        sV[128 + t] = pab[t];
        sV[192 + t] = lng[t];
        sV[256 + t] = lnb[t];
        sV[320 + t] = peg[t];
        sV[384 + t] = peb[t];
        sV[576 + t] = b2[t];
    }
    if (t < 128) sV[448 + t] = b1[t];
    __syncthreads();

    const float *pa0 = sV, *pa1 = sV + 64, *pbv = sV + 128,
                *sing = sV + 192, *sinb = sV + 256,
                *speg = sV + 320, *speb = sV + 384,
                *sb1 = sV + 448, *sb2v = sV + 576;

    for (int ti = 0; ti < 4; ti++) {
        int tile = blockIdx.x * 4 + ti;          // 8192 tiles of 64 rows
        int rowbase = tile * 64;

        for (int rr = warp; rr < 64; rr += 8) {
            const float* rp = inp + (size_t)(rowbase + rr) * 66;
            float x0 = rp[lane], x1 = rp[lane + 32];
            float s1 = x0 + x1, s2 = x0 * x0 + x1 * x1;
            #pragma unroll
            for (int o = 16; o; o >>= 1) {
                s1 += __shfl_xor_sync(0xffffffffu, s1, o);
                s2 += __shfl_xor_sync(0xffffffffu, s2, o);
            }
            float mu = s1 * 0.015625f;
            float var = s2 * 0.015625f - mu * mu;
            float rs = rsqrtf(var + LNEPS);
            sX[rr * 72 + lane]      = __float2bfloat16((x0 - mu) * rs * sing[lane]      + sinb[lane]);
            sX[rr * 72 + lane + 32] = __float2bfloat16((x1 - mu) * rs * sing[lane + 32] + sinb[lane + 32]);
            if (lane < 2) sG[rr * 2 + lane] = rp[64 + lane];
        }
        __syncthreads();

        #pragma unroll 1
        for (int pass = 0; pass < 2; pass++) {
            const u32 sbW = pass ? sbWv : sbWk;
            unsigned* outg = pass ? g_vh : g_kh;

            {
                float acc[4][4];
                #pragma unroll
                for (int s = 0; s < 4; s++)
                    #pragma unroll
                    for (int j = 0; j < 4; j++) acc[s][j] = 0.f;

                #pragma unroll
                for (int ks = 0; ks < 4; ks++) {
                    u32 a[4];
                    ldsm_x4(a, sbX + ((mt * 16 + l15) * 72 + ks * 16 + lh * 8) * 2);
                    #pragma unroll
                    for (int s = 0; s < 4; s++) {
                        u32 b[2];
                        int nb = ng * 32 + s * 8;
                        ldsm_x2t(b, sbW + ((ks * 16 + l15) * 72 + nb) * 2);
                        mma_bf16(acc[s], a, b);
                    }
                }
                int r0 = mt * 16 + lr, r1 = r0 + 8;
                float gx0 = sG[r0 * 2], gy0 = sG[r0 * 2 + 1];
                float gx1 = sG[r1 * 2], gy1 = sG[r1 * 2 + 1];
                #pragma unroll
                for (int s = 0; s < 4; s++) {
                    int c = ng * 32 + s * 8 + lc;
                    float p0a = pa0[c], p0b = pa0[c + 1];
                    float p1a = pa1[c], p1b = pa1[c + 1];
                    float pba = pbv[c], pbb = pbv[c + 1];
                    *(float2*)&sTf[r0 * 66 + c] =
                        make_float2(acc[s][0] + gx0 * p0a + gy0 * p1a + pba,
                                    acc[s][1] + gx0 * p0b + gy0 * p1b + pbb);
                    *(float2*)&sTf[r1 * 66 + c] =
                        make_float2(acc[s][2] + gx1 * p0a + gy1 * p1a + pba,
                                    acc[s][3] + gx1 * p0b + gy1 * p1b + pbb);
                }
            }
            __syncthreads();

            for (int rr = warp; rr < 64; rr += 8) {
                float x0 = sTf[rr * 66 + lane], x1 = sTf[rr * 66 + lane + 32];
                float s1 = x0 + x1, s2 = x0 * x0 + x1 * x1;
                #pragma unroll
                for (int o = 16; o; o >>= 1) {
                    s1 += __shfl_xor_sync(0xffffffffu, s1, o);
                    s2 += __shfl_xor_sync(0xffffffffu, s2, o);
                }
                float mu = s1 * 0.015625f;
                float var = s2 * 0.015625f - mu * mu;
                float rs = rsqrtf(var + LNEPS);
                sTb[rr * 72 + lane]      = __float2bfloat16((x0 - mu) * rs * speg[lane]      + speb[lane]);
                sTb[rr * 72 + lane + 32] = __float2bfloat16((x1 - mu) * rs * speg[lane + 32] + speb[lane + 32]);
            }
            __syncthreads();

            {
                float acc[8][4];
                #pragma unroll
                for (int s = 0; s < 8; s++)
                    #pragma unroll
                    for (int j = 0; j < 4; j++) acc[s][j] = 0.f;

                #pragma unroll
                for (int ks = 0; ks < 4; ks++) {
                    u32 a[4];
                    ldsm_x4(a, sbTb + ((mt * 16 + l15) * 72 + ks * 16 + lh * 8) * 2);
                    #pragma unroll
                    for (int s = 0; s < 8; s++) {
                        u32 b[2];
                        int nb = ng * 64 + s * 8;
                        ldsm_x2t(b, sbW1 + ((ks * 16 + l15) * 136 + nb) * 2);
                        mma_bf16(acc[s], a, b);
                    }
                }
                __syncthreads();   // Tf reads done before H overwrite (alias safety)
                int r0 = mt * 16 + lr, r1 = r0 + 8;
                #pragma unroll
                for (int s = 0; s < 8; s++) {
                    int c = ng * 64 + s * 8 + lc;
                    float ba = sb1[c], bb = sb1[c + 1];
                    *(u32*)&sHb[r0 * 136 + c] =
                        bf2u(fmaxf(acc[s][0] + ba, 0.f), fmaxf(acc[s][1] + bb, 0.f));
                    *(u32*)&sHb[r1 * 136 + c] =
                        bf2u(fmaxf(acc[s][2] + ba, 0.f), fmaxf(acc[s][3] + bb, 0.f));
                }
            }
            __syncthreads();

            {
                float acc[4][4];
                #pragma unroll
                for (int s = 0; s < 4; s++)
                    #pragma unroll
                    for (int j = 0; j < 4; j++) acc[s][j] = 0.f;

                #pragma unroll
                for (int ks = 0; ks < 8; ks++) {
                    u32 a[4];
                    ldsm_x4(a, sbHb + ((mt * 16 + l15) * 136 + ks * 16 + lh * 8) * 2);
                    #pragma unroll
                    for (int s = 0; s < 4; s++) {
                        u32 b[2];
                        int nb = ng * 32 + s * 8;
                        ldsm_x2t(b, sbW2 + ((ks * 16 + l15) * 72 + nb) * 2);
                        mma_bf16(acc[s], a, b);
                    }
                }
                int r0 = mt * 16 + lr, r1 = r0 + 8;
                #pragma unroll
                for (int s = 0; s < 4; s++) {
                    int c = ng * 32 + s * 8 + lc;
                    float ba = sb2v[c], bb = sb2v[c + 1];
                    outg[(size_t)(rowbase + r0) * 32 + (c >> 1)] =
                        bf2u(acc[s][0] + ba, acc[s][1] + bb);
                    outg[(size_t)(rowbase + r1) * 32 + (c >> 1)] =
                        bf2u(acc[s][2] + ba, acc[s][3] + bb);
                }
            }
            __syncthreads();
        }
    }
}

// ---------------------------------------------------------------------------
// initq: s = broadcast(slots); q = LN(s; ln_s) @ Wq  (one block per b)
// ---------------------------------------------------------------------------
__global__ __launch_bounds__(256) void initq_kernel(
    const float* __restrict__ slots,
    const float* __restrict__ lnsg, const float* __restrict__ lnsb,
    const float* __restrict__ Wq)
{
    __shared__ float ss[512], sln[512];
    int b = blockIdx.x, t = threadIdx.x, warp = t >> 5, lane = t & 31;
    for (int i = t; i < 512; i += 256) {
        float v = slots[i];
        g_s[b * 512 + i] = v;
        ss[i] = v;
    }
    __syncthreads();
    {
        const float* row = ss + warp * 64;
        float x0 = row[lane], x1 = row[lane + 32];
        float s1 = x0 + x1, s2 = x0 * x0 + x1 * x1;
        #pragma unroll
        for (int o = 16; o; o >>= 1) {
            s1 += __shfl_xor_sync(0xffffffffu, s1, o);
            s2 += __shfl_xor_sync(0xffffffffu, s2, o);
        }
        float mu = s1 * 0.015625f;
        float var = s2 * 0.015625f - mu * mu;
        float rs = rsqrtf(var + LNEPS);
        sln[warp * 64 + lane]      = (x0 - mu) * rs * lnsg[lane]      + lnsb[lane];
        sln[warp * 64 + lane + 32] = (x1 - mu) * rs * lnsg[lane + 32] + lnsb[lane + 32];
    }
    __syncthreads();
    for (int i = t; i < 512; i += 256) {
        int s = i >> 6, c = i & 63;
        float a = 0.f;
        #pragma unroll 8
        for (int d = 0; d < 64; d++) a += sln[s * 64 + d] * Wq[d * 64 + c];
        g_q[b * 512 + i] = a;
    }
}

// ---------------------------------------------------------------------------
// Attention + fused slot update (last block per batch).
// smem: qTb bf16[64][8] @0 (1024) | sKu u32 per-warp [32][36] @1024 (36864) |
//       sAb f32 per-warp [32][8] @37888 (8192) | wacc [8][520] @46080 (16640)
//       -> 62720 B (3 CTAs/SM). Update tail overlays the whole region.
// ---------------------------------------------------------------------------
#define ATTN_SMEM_BYTES 62720

__global__ __launch_bounds__(256, 3) void attn_kernel(
    const float* __restrict__ W_ih, const float* __restrict__ W_hh,
    const float* __restrict__ b_ih, const float* __restrict__ b_hh,
    const float* __restrict__ lnmg, const float* __restrict__ lnmb,
    const float* __restrict__ mW1,  const float* __restrict__ mb1,
    const float* __restrict__ mW2,  const float* __restrict__ mb2,
    const float* __restrict__ lnsg, const float* __restrict__ lnsb,
    const float* __restrict__ Wq,
    float* __restrict__ dout)
{
    extern __shared__ char smc[];
    __nv_bfloat16* qTb = (__nv_bfloat16*)smc;     // [64][8]
    u32*   sKu  = (u32*)(smc + 1024);             // per-warp [32][36]
    float* sAb  = (float*)(smc + 37888);          // per-warp [32][8]
    float* wacc = (float*)(smc + 46080);          // [8][520]
    __shared__ int sLast;

    u32 sb = (u32)__cvta_generic_to_shared(smc);
    const u32 sbQ = sb, sbK = sb + 1024;

    int b = blockIdx.x >> 6, pb = blockIdx.x & 63;
    int t = threadIdx.x, warp = t >> 5, lane = t & 31;
    const int l15 = lane & 15, lh = lane >> 4;
    const int q = lane >> 2, c0 = (lane & 3) * 2;

    for (int i = t; i < 512; i += 256) {
        int s = i >> 6, d = i & 63;
        qTb[d * 8 + s] = __float2bfloat16(g_q[b * 512 + i]);
    }
    __syncthreads();

    u32 qf[4][2];
    #pragma unroll
    for (int kc = 0; kc < 4; kc++)
        ldsm_x2t(qf[kc], sbQ + ((kc * 16 + l15) * 8) * 2);

    size_t rowbase = (size_t)b * N_ + pb * 256 + warp * 32;
    const unsigned* kp = g_kh + rowbase * 32;
    const unsigned* vp = g_vh + rowbase * 32;

    // stage k tile; v loads into registers (latency hides behind logits/softmax)
    u32* mk = sKu + warp * 1152;
    const u32 wbase = sbK + warp * 4608;
    #pragma unroll
    for (int i = 0; i < 32; i++) mk[i * 36 + lane] = kp[i * 32 + lane];
    u32 vreg[32];
    #pragma unroll
    for (int i = 0; i < 32; i++) vreg[i] = vp[i * 32 + lane];
    __syncwarp();

    // logits via HMMA: L[32x8] = K[32x64] @ Q^T
    float acc[2][4];
    #pragma unroll
    for (int m = 0; m < 2; m++)
        #pragma unroll
        for (int j = 0; j < 4; j++) acc[m][j] = 0.f;
    #pragma unroll
    for (int m = 0; m < 2; m++) {
        #pragma unroll
        for (int kc = 0; kc < 4; kc++) {
            u32 a[4];
            ldsm_x4(a, wbase + ((m * 16 + l15) * 72 + kc * 16 + lh * 8) * 2);
            mma_bf16(acc[m], a, qf[kc]);
        }
    }

    // softmax over S=8 per row (row's 8 logits live in one quad)
    float den0 = 0.f, den1 = 0.f;
    float* paw = sAb + warp * 256;
    #pragma unroll
    for (int m = 0; m < 2; m++) {
        #pragma unroll
        for (int h = 0; h < 2; h++) {
            float e0 = acc[m][h * 2]     * 0.125f;
            float e1 = acc[m][h * 2 + 1] * 0.125f;
            float mx = fmaxf(e0, e1);
            mx = fmaxf(mx, __shfl_xor_sync(0xffffffffu, mx, 1));
            mx = fmaxf(mx, __shfl_xor_sync(0xffffffffu, mx, 2));
            e0 = __expf(e0 - mx); e1 = __expf(e1 - mx);
            float se = e0 + e1;
            se += __shfl_xor_sync(0xffffffffu, se, 1);
            se += __shfl_xor_sync(0xffffffffu, se, 2);
            float inv = 1.f / se;
            e0 = e0 * inv + ATTN_EPS;
            e1 = e1 * inv + ATTN_EPS;
            int row = m * 16 + h * 8 + q;
            paw[row * 8 + c0]     = e0;
            paw[row * 8 + c0 + 1] = e1;
            den0 += e0; den1 += e1;
        }
    }
    den0 += __shfl_xor_sync(0xffffffffu, den0, 4);
    den0 += __shfl_xor_sync(0xffffffffu, den0, 8);
    den0 += __shfl_xor_sync(0xffffffffu, den0, 16);
    den1 += __shfl_xor_sync(0xffffffffu, den1, 4);
    den1 += __shfl_xor_sync(0xffffffffu, den1, 8);
    den1 += __shfl_xor_sync(0xffffffffu, den1, 16);
    __syncwarp();

    // numer[s][2 cols per lane] over the 32 rows (v from registers)
    float acc0[8], acc1[8];
    #pragma unroll
    for (int s = 0; s < 8; s++) { acc0[s] = 0.f; acc1[s] = 0.f; }
    #pragma unroll 4
    for (int i = 0; i < 32; i++) {
        float2 v = u2f2(vreg[i]);
        float4 a0 = *(const float4*)(paw + i * 8);
        float4 a1 = *(const float4*)(paw + i * 8 + 4);
        acc0[0] += a0.x * v.x; acc1[0] += a0.x * v.y;
        acc0[1] += a0.y * v.x; acc1[1] += a0.y * v.y;
        acc0[2] += a0.z * v.x; acc1[2] += a0.z * v.y;
        acc0[3] += a0.w * v.x; acc1[3] += a0.w * v.y;
        acc0[4] += a1.x * v.x; acc1[4] += a1.x * v.y;
        acc0[5] += a1.y * v.x; acc1[5] += a1.y * v.y;
        acc0[6] += a1.z * v.x; acc1[6] += a1.z * v.y;
        acc0[7] += a1.w * v.x; acc1[7] += a1.w * v.y;
    }

    float* wa = wacc + warp * 520;
    #pragma unroll
    for (int s = 0; s < 8; s++) {
        wa[s * 64 + lane * 2]     = acc0[s];
        wa[s * 64 + lane * 2 + 1] = acc1[s];
    }
    if (lane < 4) {
        wa[512 + c0]     = den0;
        wa[512 + c0 + 1] = den1;
    }
    __syncthreads();

    float* dst = g_part + (size_t)blockIdx.x * 520;
    for (int i = t; i < 520; i += 256) {
        float v = 0.f;
        #pragma unroll
        for (int w = 0; w < 8; w++) v += wacc[w * 520 + i];
        dst[i] = v;
    }

    // ---- arrival protocol ----
    __threadfence();
    __syncthreads();
    if (t == 0) {
        unsigned old = atomicAdd(&g_ctr[b], 1u);
        sLast = ((old & 63u) == 63u);
    }
    __syncthreads();
    if (!sLast) return;
    __threadfence();

    // =========================================================================
    // Fused slot update (this block is the last arriver for batch b).
    // Overlay scratch on the (now dead) attn smem.
    // =========================================================================
    float* red  = (float*)smc;          // 520
    float* uu   = red + 520;            // 512
    float* prev = uu + 512;             // 512
    float* gx   = prev + 512;           // 1536
    float* gh   = gx + 1536;            // 1536
    float* snew = gh + 1536;            // 512
    float* sln  = snew + 512;           // 512
    float* h1   = sln + 512;            // 1024  (total 6664 floats = 26656 B)

    for (int i = t; i < 520; i += 256) {
        const float* p = g_part + (size_t)(b * 64) * 520 + i;
        float v = 0.f;
        #pragma unroll 8
        for (int pp = 0; pp < 64; pp++) v += p[pp * 520];
        red[i] = v;
    }
    for (int i = t; i < 512; i += 256) prev[i] = g_s[b * 512 + i];
    __syncthreads();

    for (int i = t; i < 512; i += 256) uu[i] = red[i] / red[512 + (i >> 6)];
    __syncthreads();

    for (int i = t; i < 1536; i += 256) {
        int s = i / 192, j = i - s * 192;
        float ax = b_ih[j], ah = b_hh[j];
        const float* us = uu + s * 64;
        const float* ps = prev + s * 64;
        #pragma unroll 8
        for (int d = 0; d < 64; d++) {
            ax += us[d] * W_ih[d * 192 + j];
            ah += ps[d] * W_hh[d * 192 + j];
        }
        gx[i] = ax; gh[i] = ah;
    }
    __syncthreads();

    for (int i = t; i < 512; i += 256) {
        int s = i >> 6, dd = i & 63;
        float xr = gx[s * 192 + dd], xz = gx[s * 192 + 64 + dd], xn = gx[s * 192 + 128 + dd];
        float hr = gh[s * 192 + dd], hz = gh[s * 192 + 64 + dd], hn = gh[s * 192 + 128 + dd];
        float r_ = 1.f / (1.f + __expf(-(xr + hr)));
        float z  = 1.f / (1.f + __expf(-(xz + hz)));
        float nn = tanhf(xn + r_ * hn);
        snew[i] = (1.f - z) * nn + z * prev[i];
    }
    __syncthreads();

    // LN(snew; ln_m): warp per slot
    {
        const float* row = snew + warp * 64;
        float x0 = row[lane], x1 = row[lane + 32];
        float s1 = x0 + x1, s2 = x0 * x0 + x1 * x1;
        #pragma unroll
        for (int o = 16; o; o >>= 1) {
            s1 += __shfl_xor_sync(0xffffffffu, s1, o);
            s2 += __shfl_xor_sync(0xffffffffu, s2, o);
        }
        float mu = s1 * 0.015625f;
        float var = s2 * 0.015625f - mu * mu;
        float rs = rsqrtf(var + LNEPS);
        sln[warp * 64 + lane]      = (x0 - mu) * rs * lnmg[lane]      + lnmb[lane];
        sln[warp * 64 + lane + 32] = (x1 - mu) * rs * lnmg[lane + 32] + lnmb[lane + 32];
    }
    __syncthreads();

    for (int i = t; i < 1024; i += 256) {
        int s = i >> 7, j = i & 127;
        float a = mb1[j];
        const float* r = sln + s * 64;
        #pragma unroll 8
        for (int d = 0; d < 64; d++) a += r[d] * mW1[d * 128 + j];
        h1[i] = fmaxf(a, 0.f);
    }
    __syncthreads();

    for (int i = t; i < 512; i += 256) {
        int s = i >> 6, c = i & 63;
        float a = mb2[c];
        const float* r = h1 + s * 128;
        #pragma unroll 8
        for (int k = 0; k < 128; k++) a += r[k] * mW2[k * 64 + c];
        float val = snew[i] + a;
        g_s[b * 512 + i] = val;
        dout[b * 512 + i] = val;
        uu[i] = val;   // reuse for next-q LN
    }
    __syncthreads();

    // fused next q: LN(s_new; ln_s) @ Wq
    {
        const float* row = uu + warp * 64;
        float x0 = row[lane], x1 = row[lane + 32];
        float s1 = x0 + x1, s2 = x0 * x0 + x1 * x1;
        #pragma unroll
        for (int o = 16; o; o >>= 1) {
            s1 += __shfl_xor_sync(0xffffffffu, s1, o);
            s2 += __shfl_xor_sync(0xffffffffu, s2, o);
        }
        float mu = s1 * 0.015625f;
        float var = s2 * 0.015625f - mu * mu;
        float rs = rsqrtf(var + LNEPS);
        sln[warp * 64 + lane]      = (x0 - mu) * rs * lnsg[lane]      + lnsb[lane];
        sln[warp * 64 + lane + 32] = (x1 - mu) * rs * lnsg[lane + 32] + lnsb[lane + 32];
    }
    __syncthreads();
    for (int i = t; i < 512; i += 256) {
        int s = i >> 6, c = i & 63;
        float a = 0.f;
        #pragma unroll 8
        for (int d = 0; d < 64; d++) a += sln[s * 64 + d] * Wq[d * 64 + c];
        g_q[b * 512 + i] = a;
    }
}

// ---------------------------------------------------------------------------
extern "C" void kernel_launch(void* const* d_in, const int* in_sizes, int n_in,
                              void* d_out, int out_size)
{
    (void)in_sizes; (void)n_in; (void)out_size;
    const float* inputs  = (const float*)d_in[0];
    const float* slots   = (const float*)d_in[1];
    const float* ln_in_g = (const float*)d_in[2];
    const float* ln_in_b = (const float*)d_in[3];
    const float* ln_s_g  = (const float*)d_in[4];
    const float* ln_s_b  = (const float*)d_in[5];
    const float* ln_m_g  = (const float*)d_in[6];
    const float* ln_m_b  = (const float*)d_in[7];
    const float* Wq      = (const float*)d_in[8];
    const float* Wk      = (const float*)d_in[9];
    const float* Wv      = (const float*)d_in[10];
    const float* W_ih    = (const float*)d_in[11];
    const float* W_hh    = (const float*)d_in[12];
    const float* b_ih    = (const float*)d_in[13];
    const float* b_hh    = (const float*)d_in[14];
    const float* mlp_W1  = (const float*)d_in[15];
    const float* mlp_b1  = (const float*)d_in[16];
    const float* mlp_W2  = (const float*)d_in[17];
    const float* mlp_b2  = (const float*)d_in[18];
    const float* pa_W    = (const float*)d_in[19];
    const float* pa_b    = (const float*)d_in[20];
    const float* pe_g    = (const float*)d_in[21];
    const float* pe_b    = (const float*)d_in[22];
    const float* pe_W1   = (const float*)d_in[23];
    const float* pe_b1   = (const float*)d_in[24];
    const float* pe_W2   = (const float*)d_in[25];
    const float* pe_b2   = (const float*)d_in[26];
    float* out = (float*)d_out;

    static int configured = 0;
    if (!configured) {
        cudaFuncSetAttribute(preprocess_kernel,
                             cudaFuncAttributeMaxDynamicSharedMemorySize, PRE_SMEM_BYTES);
        cudaFuncSetAttribute(attn_kernel,
                             cudaFuncAttributeMaxDynamicSharedMemorySize, ATTN_SMEM_BYTES);
        configured = 1;
    }

    preprocess_kernel<<<2048, 256, PRE_SMEM_BYTES>>>(
        inputs, ln_in_g, ln_in_b, Wk, Wv, pa_W, pa_b, pe_g, pe_b,
        pe_W1, pe_b1, pe_W2, pe_b2);

    initq_kernel<<<32, 256>>>(slots, ln_s_g, ln_s_b, Wq);

    for (int it = 0; it < 3; it++) {
        attn_kernel<<<2048, 256, ATTN_SMEM_BYTES>>>(
            W_ih, W_hh, b_ih, b_hh, ln_m_g, ln_m_b,
            mlp_W1, mlp_b1, mlp_W2, mlp_b2,
            ln_s_g, ln_s_b, Wq, out);
    }
}

// round 15
// speedup vs baseline: 1.0676x; 1.0676x over previous
#include <cuda_runtime.h>
#include <cuda_bf16.h>
#include <cmath>

#define B_ 32
#define N_ 16384
#define D_ 64
#define S_ 8
#define H_ 128
#define LNEPS 1e-5f
#define ATTN_EPS 1e-8f

typedef unsigned long long ull;
typedef unsigned int u32;

// ---------------- scratch (device globals; no allocations allowed) ----------
__device__ unsigned g_kh[B_ * N_ * 32];   // k_pos bf16x2 (64 MB)
__device__ unsigned g_vh[B_ * N_ * 32];   // v_pos bf16x2 (64 MB)
__device__ float g_q[B_ * S_ * D_];
__device__ float g_s[B_ * S_ * D_];
__device__ float g_part[B_ * 32 * 520];   // per-(b, partial-block) numer(512)+den(8)

// ---------------- helpers ----------------------------------------------------
__device__ __forceinline__ unsigned bf2u(float a, float b) {
    __nv_bfloat162 h = __float22bfloat162_rn(make_float2(a, b));
    return *(unsigned*)&h;
}
__device__ __forceinline__ float2 u2f2(unsigned u) {
    __nv_bfloat162 h = *(__nv_bfloat162*)&u;
    return __bfloat1622float2(h);
}
__device__ __forceinline__ void ldsm_x4(u32 a[4], u32 addr) {
    asm volatile("ldmatrix.sync.aligned.m8n8.x4.shared.b16 {%0,%1,%2,%3}, [%4];"
                 : "=r"(a[0]), "=r"(a[1]), "=r"(a[2]), "=r"(a[3]) : "r"(addr));
}
__device__ __forceinline__ void ldsm_x2t(u32 b[2], u32 addr) {
    asm volatile("ldmatrix.sync.aligned.m8n8.x2.trans.shared.b16 {%0,%1}, [%2];"
                 : "=r"(b[0]), "=r"(b[1]) : "r"(addr));
}
__device__ __forceinline__ void mma_bf16(float d[4], const u32 a[4], const u32 b[2]) {
    asm volatile("mma.sync.aligned.m16n8k16.row.col.f32.bf16.bf16.f32 "
                 "{%0,%1,%2,%3},{%4,%5,%6,%7},{%8,%9},{%0,%1,%2,%3};"
                 : "+f"(d[0]), "+f"(d[1]), "+f"(d[2]), "+f"(d[3])
                 : "r"(a[0]), "r"(a[1]), "r"(a[2]), "r"(a[3]), "r"(b[0]), "r"(b[1]));
}

// ---------------------------------------------------------------------------
// Kernel 1: fused preprocessing (unchanged from R11-R13 best).
// ---------------------------------------------------------------------------
#define PRE_SMEM_BYTES 93184

__global__ __launch_bounds__(256, 2) void preprocess_kernel(
    const float* __restrict__ inp,
    const float* __restrict__ lng, const float* __restrict__ lnb,
    const float* __restrict__ Wk,  const float* __restrict__ Wv,
    const float* __restrict__ paW, const float* __restrict__ pab,
    const float* __restrict__ peg, const float* __restrict__ peb,
    const float* __restrict__ W1,  const float* __restrict__ b1,
    const float* __restrict__ W2,  const float* __restrict__ b2)
{
    extern __shared__ char smem[];
    __nv_bfloat16* sWk = (__nv_bfloat16*)(smem);
    __nv_bfloat16* sWv = (__nv_bfloat16*)(smem + 9216);
    __nv_bfloat16* sW1 = (__nv_bfloat16*)(smem + 18432);
    __nv_bfloat16* sW2 = (__nv_bfloat16*)(smem + 35840);
    __nv_bfloat16* sX  = (__nv_bfloat16*)(smem + 54272);
    float*         sTf = (float*)(smem + 63488);          // aliased with sHb
    __nv_bfloat16* sHb = (__nv_bfloat16*)(smem + 63488);
    __nv_bfloat16* sTb = (__nv_bfloat16*)(smem + 80896);
    float*         sV  = (float*)(smem + 90112);
    float*         sG  = (float*)(smem + 92672);

    u32 sb = (u32)__cvta_generic_to_shared(smem);
    const u32 sbWk = sb, sbWv = sb + 9216, sbW1 = sb + 18432, sbW2 = sb + 35840;
    const u32 sbX = sb + 54272, sbHb = sb + 63488, sbTb = sb + 80896;

    const int t = threadIdx.x, warp = t >> 5, lane = t & 31;
    const int mt = warp >> 1, ng = warp & 1;
    const int l15 = lane & 15, lh = lane >> 4, lr = lane >> 2, lc = (lane & 3) * 2;

    for (int i = t; i < 4096; i += 256) {
        int r = i >> 6, c = i & 63;
        sWk[r * 72 + c] = __float2bfloat16(Wk[i]);
        sWv[r * 72 + c] = __float2bfloat16(Wv[i]);
    }
    for (int i = t; i < 8192; i += 256) {
        int r1_ = i >> 7, c1_ = i & 127;
        sW1[r1_ * 136 + c1_] = __float2bfloat16(W1[i]);
        int r2_ = i >> 6, c2_ = i & 63;
        sW2[r2_ * 72 + c2_] = __float2bfloat16(W2[i]);
    }
    if (t < 64) {
        sV[t]       = paW[t];
        sV[64 + t]  = paW[64 + t];
        sV[128 + t] = pab[t];
        sV[192 + t] = lng[t];
        sV[256 + t] = lnb[t];
        sV[320 + t] = peg[t];
        sV[384 + t] = peb[t];
        sV[576 + t] = b2[t];
    }
    if (t < 128) sV[448 + t] = b1[t];
    __syncthreads();

    const float *pa0 = sV, *pa1 = sV + 64, *pbv = sV + 128,
                *sing = sV + 192, *sinb = sV + 256,
                *speg = sV + 320, *speb = sV + 384,
                *sb1 = sV + 448, *sb2v = sV + 576;

    for (int ti = 0; ti < 4; ti++) {
        int tile = blockIdx.x * 4 + ti;          // 8192 tiles of 64 rows
        int rowbase = tile * 64;

        for (int rr = warp; rr < 64; rr += 8) {
            const float* rp = inp + (size_t)(rowbase + rr) * 66;
            float x0 = rp[lane], x1 = rp[lane + 32];
            float s1 = x0 + x1, s2 = x0 * x0 + x1 * x1;
            #pragma unroll
            for (int o = 16; o; o >>= 1) {
                s1 += __shfl_xor_sync(0xffffffffu, s1, o);
                s2 += __shfl_xor_sync(0xffffffffu, s2, o);
            }
            float mu = s1 * 0.015625f;
            float var = s2 * 0.015625f - mu * mu;
            float rs = rsqrtf(var + LNEPS);
            sX[rr * 72 + lane]      = __float2bfloat16((x0 - mu) * rs * sing[lane]      + sinb[lane]);
            sX[rr * 72 + lane + 32] = __float2bfloat16((x1 - mu) * rs * sing[lane + 32] + sinb[lane + 32]);
            if (lane < 2) sG[rr * 2 + lane] = rp[64 + lane];
        }
        __syncthreads();

        #pragma unroll 1
        for (int pass = 0; pass < 2; pass++) {
            const u32 sbW = pass ? sbWv : sbWk;
            unsigned* outg = pass ? g_vh : g_kh;

            {
                float acc[4][4];
                #pragma unroll
                for (int s = 0; s < 4; s++)
                    #pragma unroll
                    for (int j = 0; j < 4; j++) acc[s][j] = 0.f;

                #pragma unroll
                for (int ks = 0; ks < 4; ks++) {
                    u32 a[4];
                    ldsm_x4(a, sbX + ((mt * 16 + l15) * 72 + ks * 16 + lh * 8) * 2);
                    #pragma unroll
                    for (int s = 0; s < 4; s++) {
                        u32 b[2];
                        int nb = ng * 32 + s * 8;
                        ldsm_x2t(b, sbW + ((ks * 16 + l15) * 72 + nb) * 2);
                        mma_bf16(acc[s], a, b);
                    }
                }
                int r0 = mt * 16 + lr, r1 = r0 + 8;
                float gx0 = sG[r0 * 2], gy0 = sG[r0 * 2 + 1];
                float gx1 = sG[r1 * 2], gy1 = sG[r1 * 2 + 1];
                #pragma unroll
                for (int s = 0; s < 4; s++) {
                    int c = ng * 32 + s * 8 + lc;
                    float p0a = pa0[c], p0b = pa0[c + 1];
                    float p1a = pa1[c], p1b = pa1[c + 1];
                    float pba = pbv[c], pbb = pbv[c + 1];
                    *(float2*)&sTf[r0 * 66 + c] =
                        make_float2(acc[s][0] + gx0 * p0a + gy0 * p1a + pba,
                                    acc[s][1] + gx0 * p0b + gy0 * p1b + pbb);
                    *(float2*)&sTf[r1 * 66 + c] =
                        make_float2(acc[s][2] + gx1 * p0a + gy1 * p1a + pba,
                                    acc[s][3] + gx1 * p0b + gy1 * p1b + pbb);
                }
            }
            __syncthreads();

            for (int rr = warp; rr < 64; rr += 8) {
                float x0 = sTf[rr * 66 + lane], x1 = sTf[rr * 66 + lane + 32];
                float s1 = x0 + x1, s2 = x0 * x0 + x1 * x1;
                #pragma unroll
                for (int o = 16; o; o >>= 1) {
                    s1 += __shfl_xor_sync(0xffffffffu, s1, o);
                    s2 += __shfl_xor_sync(0xffffffffu, s2, o);
                }
                float mu = s1 * 0.015625f;
                float var = s2 * 0.015625f - mu * mu;
                float rs = rsqrtf(var + LNEPS);
                sTb[rr * 72 + lane]      = __float2bfloat16((x0 - mu) * rs * speg[lane]      + speb[lane]);
                sTb[rr * 72 + lane + 32] = __float2bfloat16((x1 - mu) * rs * speg[lane + 32] + speb[lane + 32]);
            }
            __syncthreads();

            {
                float acc[8][4];
                #pragma unroll
                for (int s = 0; s < 8; s++)
                    #pragma unroll
                    for (int j = 0; j < 4; j++) acc[s][j] = 0.f;

                #pragma unroll
                for (int ks = 0; ks < 4; ks++) {
                    u32 a[4];
                    ldsm_x4(a, sbTb + ((mt * 16 + l15) * 72 + ks * 16 + lh * 8) * 2);
                    #pragma unroll
                    for (int s = 0; s < 8; s++) {
                        u32 b[2];
                        int nb = ng * 64 + s * 8;
                        ldsm_x2t(b, sbW1 + ((ks * 16 + l15) * 136 + nb) * 2);
                        mma_bf16(acc[s], a, b);
                    }
                }
                __syncthreads();   // Tf reads done before H overwrite (alias safety)
                int r0 = mt * 16 + lr, r1 = r0 + 8;
                #pragma unroll
                for (int s = 0; s < 8; s++) {
                    int c = ng * 64 + s * 8 + lc;
                    float ba = sb1[c], bb = sb1[c + 1];
                    *(u32*)&sHb[r0 * 136 + c] =
                        bf2u(fmaxf(acc[s][0] + ba, 0.f), fmaxf(acc[s][1] + bb, 0.f));
                    *(u32*)&sHb[r1 * 136 + c] =
                        bf2u(fmaxf(acc[s][2] + ba, 0.f), fmaxf(acc[s][3] + bb, 0.f));
                }
            }
            __syncthreads();

            {
                float acc[4][4];
                #pragma unroll
                for (int s = 0; s < 4; s++)
                    #pragma unroll
                    for (int j = 0; j < 4; j++) acc[s][j] = 0.f;

                #pragma unroll
                for (int ks = 0; ks < 8; ks++) {
                    u32 a[4];
                    ldsm_x4(a, sbHb + ((mt * 16 + l15) * 136 + ks * 16 + lh * 8) * 2);
                    #pragma unroll
                    for (int s = 0; s < 4; s++) {
                        u32 b[2];
                        int nb = ng * 32 + s * 8;
                        ldsm_x2t(b, sbW2 + ((ks * 16 + l15) * 72 + nb) * 2);
                        mma_bf16(acc[s], a, b);
                    }
                }
                int r0 = mt * 16 + lr, r1 = r0 + 8;
                #pragma unroll
                for (int s = 0; s < 4; s++) {
                    int c = ng * 32 + s * 8 + lc;
                    float ba = sb2v[c], bb = sb2v[c + 1];
                    outg[(size_t)(rowbase + r0) * 32 + (c >> 1)] =
                        bf2u(acc[s][0] + ba, acc[s][1] + bb);
                    outg[(size_t)(rowbase + r1) * 32 + (c >> 1)] =
                        bf2u(acc[s][2] + ba, acc[s][3] + bb);
                }
            }
            __syncthreads();
        }
    }
}

// ---------------------------------------------------------------------------
// initq: s = broadcast(slots); q = LN(s; ln_s) @ Wq  (one block per b)
// ---------------------------------------------------------------------------
__global__ __launch_bounds__(256) void initq_kernel(
    const float* __restrict__ slots,
    const float* __restrict__ lnsg, const float* __restrict__ lnsb,
    const float* __restrict__ Wq)
{
    __shared__ float ss[512], sln[512];
    int b = blockIdx.x, t = threadIdx.x, warp = t >> 5, lane = t & 31;
    for (int i = t; i < 512; i += 256) {
        float v = slots[i];
        g_s[b * 512 + i] = v;
        ss[i] = v;
    }
    __syncthreads();
    {
        const float* row = ss + warp * 64;
        float x0 = row[lane], x1 = row[lane + 32];
        float s1 = x0 + x1, s2 = x0 * x0 + x1 * x1;
        #pragma unroll
        for (int o = 16; o; o >>= 1) {
            s1 += __shfl_xor_sync(0xffffffffu, s1, o);
            s2 += __shfl_xor_sync(0xffffffffu, s2, o);
        }
        float mu = s1 * 0.015625f;
        float var = s2 * 0.015625f - mu * mu;
        float rs = rsqrtf(var + LNEPS);
        sln[warp * 64 + lane]      = (x0 - mu) * rs * lnsg[lane]      + lnsb[lane];
        sln[warp * 64 + lane + 32] = (x1 - mu) * rs * lnsg[lane + 32] + lnsb[lane + 32];
    }
    __syncthreads();
    for (int i = t; i < 512; i += 256) {
        int s = i >> 6, c = i & 63;
        float a = 0.f;
        #pragma unroll 8
        for (int d = 0; d < 64; d++) a += sln[s * 64 + d] * Wq[d * 64 + c];
        g_q[b * 512 + i] = a;
    }
}

// ---------------------------------------------------------------------------
// Attention: HMMA logits, 2 row-tiles per warp (512 rows/block, grid B*32).
// Accumulators persist across tiles; v preloaded to registers per tile.
// smem: qTb bf16[64][8] @0 (1024) | sKu u32 per-warp [32][36] @1024 (36864) |
//       sAb f32 per-warp [32][8] @37888 (8192) | wacc [8][520] @46080 (16640)
//       -> 62720 B (3 CTAs/SM)
// ---------------------------------------------------------------------------
#define ATTN_SMEM_BYTES 62720

__global__ __launch_bounds__(256, 3) void attn_kernel()
{
    extern __shared__ char smc[];
    __nv_bfloat16* qTb = (__nv_bfloat16*)smc;     // [64][8]
    u32*   sKu  = (u32*)(smc + 1024);             // per-warp [32][36]
    float* sAb  = (float*)(smc + 37888);          // per-warp [32][8]
    float* wacc = (float*)(smc + 46080);          // [8][520]

    u32 sb = (u32)__cvta_generic_to_shared(smc);
    const u32 sbQ = sb, sbK = sb + 1024;

    int b = blockIdx.x >> 5, pb = blockIdx.x & 31;
    int t = threadIdx.x, warp = t >> 5, lane = t & 31;
    const int l15 = lane & 15, lh = lane >> 4;
    const int q = lane >> 2, c0 = (lane & 3) * 2;

    for (int i = t; i < 512; i += 256) {
        int s = i >> 6, d = i & 63;
        qTb[d * 8 + s] = __float2bfloat16(g_q[b * 512 + i]);
    }
    __syncthreads();

    u32 qf[4][2];
    #pragma unroll
    for (int kc = 0; kc < 4; kc++)
        ldsm_x2t(qf[kc], sbQ + ((kc * 16 + l15) * 8) * 2);

    u32* mk = sKu + warp * 1152;
    const u32 wbase = sbK + warp * 4608;
    float* paw = sAb + warp * 256;

    float acc0[8], acc1[8];
    #pragma unroll
    for (int s = 0; s < 8; s++) { acc0[s] = 0.f; acc1[s] = 0.f; }
    float den0 = 0.f, den1 = 0.f;

    #pragma unroll 1
    for (int tt = 0; tt < 2; tt++) {
        size_t rowbase = (size_t)b * N_ + pb * 512 + tt * 256 + warp * 32;
        const unsigned* kp = g_kh + rowbase * 32;
        const unsigned* vp = g_vh + rowbase * 32;

        __syncwarp();   // prior tile's paw reads complete before reuse
        // stage k tile; v loads into registers (latency hides behind logits)
        #pragma unroll
        for (int i = 0; i < 32; i++) mk[i * 36 + lane] = kp[i * 32 + lane];
        u32 vreg[32];
        #pragma unroll
        for (int i = 0; i < 32; i++) vreg[i] = vp[i * 32 + lane];
        __syncwarp();

        // logits via HMMA: L[32x8] = K[32x64] @ Q^T
        float acc[2][4];
        #pragma unroll
        for (int m = 0; m < 2; m++)
            #pragma unroll
            for (int j = 0; j < 4; j++) acc[m][j] = 0.f;
        #pragma unroll
        for (int m = 0; m < 2; m++) {
            #pragma unroll
            for (int kc = 0; kc < 4; kc++) {
                u32 a[4];
                ldsm_x4(a, wbase + ((m * 16 + l15) * 72 + kc * 16 + lh * 8) * 2);
                mma_bf16(acc[m], a, qf[kc]);
            }
        }

        // softmax over S=8 per row (row's 8 logits live in one quad)
        #pragma unroll
        for (int m = 0; m < 2; m++) {
            #pragma unroll
            for (int h = 0; h < 2; h++) {
                float e0 = acc[m][h * 2]     * 0.125f;
                float e1 = acc[m][h * 2 + 1] * 0.125f;
                float mx = fmaxf(e0, e1);
                mx = fmaxf(mx, __shfl_xor_sync(0xffffffffu, mx, 1));
                mx = fmaxf(mx, __shfl_xor_sync(0xffffffffu, mx, 2));
                e0 = __expf(e0 - mx); e1 = __expf(e1 - mx);
                float se = e0 + e1;
                se += __shfl_xor_sync(0xffffffffu, se, 1);
                se += __shfl_xor_sync(0xffffffffu, se, 2);
                float inv = 1.f / se;
                e0 = e0 * inv + ATTN_EPS;
                e1 = e1 * inv + ATTN_EPS;
                int row = m * 16 + h * 8 + q;
                paw[row * 8 + c0]     = e0;
                paw[row * 8 + c0 + 1] = e1;
                den0 += e0; den1 += e1;
            }
        }
        __syncwarp();

        // numer[s][2 cols per lane] over the 32 rows (v from registers)
        #pragma unroll 4
        for (int i = 0; i < 32; i++) {
            float2 v = u2f2(vreg[i]);
            float4 a0 = *(const float4*)(paw + i * 8);
            float4 a1 = *(const float4*)(paw + i * 8 + 4);
            acc0[0] += a0.x * v.x; acc1[0] += a0.x * v.y;
            acc0[1] += a0.y * v.x; acc1[1] += a0.y * v.y;
            acc0[2] += a0.z * v.x; acc1[2] += a0.z * v.y;
            acc0[3] += a0.w * v.x; acc1[3] += a0.w * v.y;
            acc0[4] += a1.x * v.x; acc1[4] += a1.x * v.y;
            acc0[5] += a1.y * v.x; acc1[5] += a1.y * v.y;
            acc0[6] += a1.z * v.x; acc1[6] += a1.z * v.y;
            acc0[7] += a1.w * v.x; acc1[7] += a1.w * v.y;
        }
    }

    // per-slot denominators: reduce over lanes with same (lane&3)
    den0 += __shfl_xor_sync(0xffffffffu, den0, 4);
    den0 += __shfl_xor_sync(0xffffffffu, den0, 8);
    den0 += __shfl_xor_sync(0xffffffffu, den0, 16);
    den1 += __shfl_xor_sync(0xffffffffu, den1, 4);
    den1 += __shfl_xor_sync(0xffffffffu, den1, 8);
    den1 += __shfl_xor_sync(0xffffffffu, den1, 16);

    float* wa = wacc + warp * 520;
    #pragma unroll
    for (int s = 0; s < 8; s++) {
        wa[s * 64 + lane * 2]     = acc0[s];
        wa[s * 64 + lane * 2 + 1] = acc1[s];
    }
    if (lane < 4) {
        wa[512 + c0]     = den0;
        wa[512 + c0 + 1] = den1;
    }
    __syncthreads();

    float* dst = g_part + (size_t)blockIdx.x * 520;
    for (int i = t; i < 520; i += 256) {
        float v = 0.f;
        #pragma unroll
        for (int w = 0; w < 8; w++) v += wacc[w * 520 + i];
        dst[i] = v;
    }
}

// ---------------------------------------------------------------------------
// update: one block per (b, slot); 4-way parallel partial reduction over the
// 32 partial blocks.
// ---------------------------------------------------------------------------
__global__ __launch_bounds__(256) void update_kernel(
    const float* __restrict__ W_ih, const float* __restrict__ W_hh,
    const float* __restrict__ b_ih, const float* __restrict__ b_hh,
    const float* __restrict__ lnmg, const float* __restrict__ lnmb,
    const float* __restrict__ mW1,  const float* __restrict__ mb1,
    const float* __restrict__ mW2,  const float* __restrict__ mb2,
    const float* __restrict__ lnsg, const float* __restrict__ lnsb,
    const float* __restrict__ Wq,
    float* __restrict__ dout)
{
    __shared__ float sRed[4][64], sDen[4];
    __shared__ float u[64], prev[64], gx[192], gh[192];
    __shared__ float snew[64], sln[64], h1[128];
    int b = blockIdx.x >> 3, s = blockIdx.x & 7;
    int t = threadIdx.x, warp = t >> 5, lane = t & 31;
    int g = t >> 6, e = t & 63;

    // ---- parallel reduction: group g sums partial blocks [8g, 8g+8) ----
    {
        const float* p = g_part + (size_t)(b * 32) * 520 + (size_t)g * 8 * 520;
        float v = 0.f;
        #pragma unroll
        for (int j = 0; j < 8; j++) v += p[j * 520 + s * 64 + e];
        sRed[g][e] = v;
        if (t < 4) {
            const float* pd = g_part + (size_t)(b * 32) * 520 + (size_t)t * 8 * 520;
            float dv = 0.f;
            #pragma unroll
            for (int j = 0; j < 8; j++) dv += pd[j * 520 + 512 + s];
            sDen[t] = dv;
        }
        if (t >= 64 && t < 128) prev[e] = g_s[b * 512 + s * 64 + e];
    }
    __syncthreads();

    if (t < 64) {
        float den = sDen[0] + sDen[1] + sDen[2] + sDen[3];
        u[t] = (sRed[0][t] + sRed[1][t] + sRed[2][t] + sRed[3][t]) / den;
    }
    __syncthreads();

    if (t < 192) {
        float ax = b_ih[t], ah = b_hh[t];
        #pragma unroll 8
        for (int d = 0; d < 64; d++) {
            ax += u[d]    * W_ih[d * 192 + t];
            ah += prev[d] * W_hh[d * 192 + t];
        }
        gx[t] = ax; gh[t] = ah;
    }
    __syncthreads();

    if (t < 64) {
        float xr = gx[t], xz = gx[64 + t], xn = gx[128 + t];
        float hr = gh[t], hz = gh[64 + t], hn = gh[128 + t];
        float r_ = 1.f / (1.f + __expf(-(xr + hr)));
        float z  = 1.f / (1.f + __expf(-(xz + hz)));
        float nn = tanhf(xn + r_ * hn);
        snew[t] = (1.f - z) * nn + z * prev[t];
    }
    __syncthreads();

    if (warp == 0) {
        float x0 = snew[lane], x1 = snew[lane + 32];
        float s1 = x0 + x1, s2 = x0 * x0 + x1 * x1;
        #pragma unroll
        for (int o = 16; o; o >>= 1) {
            s1 += __shfl_xor_sync(0xffffffffu, s1, o);
            s2 += __shfl_xor_sync(0xffffffffu, s2, o);
        }
        float mu = s1 * 0.015625f;
        float var = s2 * 0.015625f - mu * mu;
        float rs = rsqrtf(var + LNEPS);
        sln[lane]      = (x0 - mu) * rs * lnmg[lane]      + lnmb[lane];
        sln[lane + 32] = (x1 - mu) * rs * lnmg[lane + 32] + lnmb[lane + 32];
    }
    __syncthreads();

    if (t < 128) {
        float a = mb1[t];
        #pragma unroll 8
        for (int d = 0; d < 64; d++) a += sln[d] * mW1[d * 128 + t];
        h1[t] = fmaxf(a, 0.f);
    }
    __syncthreads();

    if (t < 64) {
        float a = mb2[t];
        #pragma unroll 8
        for (int k = 0; k < 128; k++) a += h1[k] * mW2[k * 64 + t];
        float val = snew[t] + a;
        g_s[b * 512 + s * 64 + t] = val;
        dout[b * 512 + s * 64 + t] = val;
        u[t] = val;   // reuse for next-q LN
    }
    __syncthreads();

    if (warp == 0) {
        float x0 = u[lane], x1 = u[lane + 32];
        float s1 = x0 + x1, s2 = x0 * x0 + x1 * x1;
        #pragma unroll
        for (int o = 16; o; o >>= 1) {
            s1 += __shfl_xor_sync(0xffffffffu, s1, o);
            s2 += __shfl_xor_sync(0xffffffffu, s2, o);
        }
        float mu = s1 * 0.015625f;
        float var = s2 * 0.015625f - mu * mu;
        float rs = rsqrtf(var + LNEPS);
        sln[lane]      = (x0 - mu) * rs * lnsg[lane]      + lnsb[lane];
        sln[lane + 32] = (x1 - mu) * rs * lnsg[lane + 32] + lnsb[lane + 32];
    }
    __syncthreads();
    if (t < 64) {
        float a = 0.f;
        #pragma unroll 8
        for (int d = 0; d < 64; d++) a += sln[d] * Wq[d * 64 + t];
        g_q[b * 512 + s * 64 + t] = a;
    }
}

// ---------------------------------------------------------------------------
extern "C" void kernel_launch(void* const* d_in, const int* in_sizes, int n_in,
                              void* d_out, int out_size)
{
    (void)in_sizes; (void)n_in; (void)out_size;
    const float* inputs  = (const float*)d_in[0];
    const float* slots   = (const float*)d_in[1];
    const float* ln_in_g = (const float*)d_in[2];
    const float* ln_in_b = (const float*)d_in[3];
    const float* ln_s_g  = (const float*)d_in[4];
    const float* ln_s_b  = (const float*)d_in[5];
    const float* ln_m_g  = (const float*)d_in[6];
    const float* ln_m_b  = (const float*)d_in[7];
    const float* Wq      = (const float*)d_in[8];
    const float* Wk      = (const float*)d_in[9];
    const float* Wv      = (const float*)d_in[10];
    const float* W_ih    = (const float*)d_in[11];
    const float* W_hh    = (const float*)d_in[12];
    const float* b_ih    = (const float*)d_in[13];
    const float* b_hh    = (const float*)d_in[14];
    const float* mlp_W1  = (const float*)d_in[15];
    const float* mlp_b1  = (const float*)d_in[16];
    const float* mlp_W2  = (const float*)d_in[17];
    const float* mlp_b2  = (const float*)d_in[18];
    const float* pa_W    = (const float*)d_in[19];
    const float* pa_b    = (const float*)d_in[20];
    const float* pe_g    = (const float*)d_in[21];
    const float* pe_b    = (const float*)d_in[22];
    const float* pe_W1   = (const float*)d_in[23];
    const float* pe_b1   = (const float*)d_in[24];
    const float* pe_W2   = (const float*)d_in[25];
    const float* pe_b2   = (const float*)d_in[26];
    float* out = (float*)d_out;

    static int configured = 0;
    if (!configured) {
        cudaFuncSetAttribute(preprocess_kernel,
                             cudaFuncAttributeMaxDynamicSharedMemorySize, PRE_SMEM_BYTES);
        cudaFuncSetAttribute(attn_kernel,
                             cudaFuncAttributeMaxDynamicSharedMemorySize, ATTN_SMEM_BYTES);
        configured = 1;
    }

    preprocess_kernel<<<2048, 256, PRE_SMEM_BYTES>>>(
        inputs, ln_in_g, ln_in_b, Wk, Wv, pa_W, pa_b, pe_g, pe_b,
        pe_W1, pe_b1, pe_W2, pe_b2);

    initq_kernel<<<32, 256>>>(slots, ln_s_g, ln_s_b, Wq);

    for (int it = 0; it < 3; it++) {
        attn_kernel<<<1024, 256, ATTN_SMEM_BYTES>>>();
        update_kernel<<<256, 256>>>(W_ih, W_hh, b_ih, b_hh,
                                    ln_m_g, ln_m_b,
                                    mlp_W1, mlp_b1, mlp_W2, mlp_b2,
                                    ln_s_g, ln_s_b, Wq, out);
    }
}

// round 16
// speedup vs baseline: 1.1468x; 1.0741x over previous
#include <cuda_runtime.h>
#include <cuda_bf16.h>
#include <cmath>

#define B_ 32
#define N_ 16384
#define D_ 64
#define S_ 8
#define H_ 128
#define LNEPS 1e-5f
#define ATTN_EPS 1e-8f

typedef unsigned long long ull;
typedef unsigned int u32;

// ---------------- scratch (device globals; no allocations allowed) ----------
__device__ unsigned g_kh[B_ * N_ * 32];   // k_pos bf16x2 (64 MB)
__device__ unsigned g_vh[B_ * N_ * 32];   // v_pos bf16x2 (64 MB)
__device__ float g_q[B_ * S_ * D_];
__device__ float g_s[B_ * S_ * D_];
__device__ float g_part[B_ * 32 * 520];   // per-(b, partial-block) numer(512)+den(8)

// ---------------- helpers ----------------------------------------------------
__device__ __forceinline__ unsigned bf2u(float a, float b) {
    __nv_bfloat162 h = __float22bfloat162_rn(make_float2(a, b));
    return *(unsigned*)&h;
}
__device__ __forceinline__ float2 u2f2(unsigned u) {
    __nv_bfloat162 h = *(__nv_bfloat162*)&u;
    return __bfloat1622float2(h);
}
__device__ __forceinline__ void ldsm_x4(u32 a[4], u32 addr) {
    asm volatile("ldmatrix.sync.aligned.m8n8.x4.shared.b16 {%0,%1,%2,%3}, [%4];"
                 : "=r"(a[0]), "=r"(a[1]), "=r"(a[2]), "=r"(a[3]) : "r"(addr));
}
__device__ __forceinline__ void ldsm_x4t(u32 a[4], u32 addr) {
    asm volatile("ldmatrix.sync.aligned.m8n8.x4.trans.shared.b16 {%0,%1,%2,%3}, [%4];"
                 : "=r"(a[0]), "=r"(a[1]), "=r"(a[2]), "=r"(a[3]) : "r"(addr));
}
__device__ __forceinline__ void ldsm_x2t(u32 b[2], u32 addr) {
    asm volatile("ldmatrix.sync.aligned.m8n8.x2.trans.shared.b16 {%0,%1}, [%2];"
                 : "=r"(b[0]), "=r"(b[1]) : "r"(addr));
}
__device__ __forceinline__ void ldsm_x2(u32 b[2], u32 addr) {
    asm volatile("ldmatrix.sync.aligned.m8n8.x2.shared.b16 {%0,%1}, [%2];"
                 : "=r"(b[0]), "=r"(b[1]) : "r"(addr));
}
__device__ __forceinline__ void mma_bf16(float d[4], const u32 a[4], const u32 b[2]) {
    asm volatile("mma.sync.aligned.m16n8k16.row.col.f32.bf16.bf16.f32 "
                 "{%0,%1,%2,%3},{%4,%5,%6,%7},{%8,%9},{%0,%1,%2,%3};"
                 : "+f"(d[0]), "+f"(d[1]), "+f"(d[2]), "+f"(d[3])
                 : "r"(a[0]), "r"(a[1]), "r"(a[2]), "r"(a[3]), "r"(b[0]), "r"(b[1]));
}

// ---------------------------------------------------------------------------
// Kernel 1: fused preprocessing (unchanged from R11-R15 best).
// ---------------------------------------------------------------------------
#define PRE_SMEM_BYTES 93184

__global__ __launch_bounds__(256, 2) void preprocess_kernel(
    const float* __restrict__ inp,
    const float* __restrict__ lng, const float* __restrict__ lnb,
    const float* __restrict__ Wk,  const float* __restrict__ Wv,
    const float* __restrict__ paW, const float* __restrict__ pab,
    const float* __restrict__ peg, const float* __restrict__ peb,
    const float* __restrict__ W1,  const float* __restrict__ b1,
    const float* __restrict__ W2,  const float* __restrict__ b2)
{
    extern __shared__ char smem[];
    __nv_bfloat16* sWk = (__nv_bfloat16*)(smem);
    __nv_bfloat16* sWv = (__nv_bfloat16*)(smem + 9216);
    __nv_bfloat16* sW1 = (__nv_bfloat16*)(smem + 18432);
    __nv_bfloat16* sW2 = (__nv_bfloat16*)(smem + 35840);
    __nv_bfloat16* sX  = (__nv_bfloat16*)(smem + 54272);
    float*         sTf = (float*)(smem + 63488);          // aliased with sHb
    __nv_bfloat16* sHb = (__nv_bfloat16*)(smem + 63488);
    __nv_bfloat16* sTb = (__nv_bfloat16*)(smem + 80896);
    float*         sV  = (float*)(smem + 90112);
    float*         sG  = (float*)(smem + 92672);

    u32 sb = (u32)__cvta_generic_to_shared(smem);
    const u32 sbWk = sb, sbWv = sb + 9216, sbW1 = sb + 18432, sbW2 = sb + 35840;
    const u32 sbX = sb + 54272, sbHb = sb + 63488, sbTb = sb + 80896;

    const int t = threadIdx.x, warp = t >> 5, lane = t & 31;
    const int mt = warp >> 1, ng = warp & 1;
    const int l15 = lane & 15, lh = lane >> 4, lr = lane >> 2, lc = (lane & 3) * 2;

    for (int i = t; i < 4096; i += 256) {
        int r = i >> 6, c = i & 63;
        sWk[r * 72 + c] = __float2bfloat16(Wk[i]);
        sWv[r * 72 + c] = __float2bfloat16(Wv[i]);
    }
    for (int i = t; i < 8192; i += 256) {
        int r1_ = i >> 7, c1_ = i & 127;
        sW1[r1_ * 136 + c1_] = __float2bfloat16(W1[i]);
        int r2_ = i >> 6, c2_ = i & 63;
        sW2[r2_ * 72 + c2_] = __float2bfloat16(W2[i]);
    }
    if (t < 64) {
        sV[t]       = paW[t];
        sV[64 + t]  = paW[64 + t];
        sV[128 + t] = pab[t];
        sV[192 + t] = lng[t];
        sV[256 + t] = lnb[t];
        sV[320 + t] = peg[t];
        sV[384 + t] = peb[t];
        sV[576 + t] = b2[t];
    }
    if (t < 128) sV[448 + t] = b1[t];
    __syncthreads();

    const float *pa0 = sV, *pa1 = sV + 64, *pbv = sV + 128,
                *sing = sV + 192, *sinb = sV + 256,
                *speg = sV + 320, *speb = sV + 384,
                *sb1 = sV + 448, *sb2v = sV + 576;

    for (int ti = 0; ti < 4; ti++) {
        int tile = blockIdx.x * 4 + ti;          // 8192 tiles of 64 rows
        int rowbase = tile * 64;

        for (int rr = warp; rr < 64; rr += 8) {
            const float* rp = inp + (size_t)(rowbase + rr) * 66;
            float x0 = rp[lane], x1 = rp[lane + 32];
            float s1 = x0 + x1, s2 = x0 * x0 + x1 * x1;
            #pragma unroll
            for (int o = 16; o; o >>= 1) {
                s1 += __shfl_xor_sync(0xffffffffu, s1, o);
                s2 += __shfl_xor_sync(0xffffffffu, s2, o);
            }
            float mu = s1 * 0.015625f;
            float var = s2 * 0.015625f - mu * mu;
            float rs = rsqrtf(var + LNEPS);
            sX[rr * 72 + lane]      = __float2bfloat16((x0 - mu) * rs * sing[lane]      + sinb[lane]);
            sX[rr * 72 + lane + 32] = __float2bfloat16((x1 - mu) * rs * sing[lane + 32] + sinb[lane + 32]);
            if (lane < 2) sG[rr * 2 + lane] = rp[64 + lane];
        }
        __syncthreads();

        #pragma unroll 1
        for (int pass = 0; pass < 2; pass++) {
            const u32 sbW = pass ? sbWv : sbWk;
            unsigned* outg = pass ? g_vh : g_kh;

            {
                float acc[4][4];
                #pragma unroll
                for (int s = 0; s < 4; s++)
                    #pragma unroll
                    for (int j = 0; j < 4; j++) acc[s][j] = 0.f;

                #pragma unroll
                for (int ks = 0; ks < 4; ks++) {
                    u32 a[4];
                    ldsm_x4(a, sbX + ((mt * 16 + l15) * 72 + ks * 16 + lh * 8) * 2);
                    #pragma unroll
                    for (int s = 0; s < 4; s++) {
                        u32 b[2];
                        int nb = ng * 32 + s * 8;
                        ldsm_x2t(b, sbW + ((ks * 16 + l15) * 72 + nb) * 2);
                        mma_bf16(acc[s], a, b);
                    }
                }
                int r0 = mt * 16 + lr, r1 = r0 + 8;
                float gx0 = sG[r0 * 2], gy0 = sG[r0 * 2 + 1];
                float gx1 = sG[r1 * 2], gy1 = sG[r1 * 2 + 1];
                #pragma unroll
                for (int s = 0; s < 4; s++) {
                    int c = ng * 32 + s * 8 + lc;
                    float p0a = pa0[c], p0b = pa0[c + 1];
                    float p1a = pa1[c], p1b = pa1[c + 1];
                    float pba = pbv[c], pbb = pbv[c + 1];
                    *(float2*)&sTf[r0 * 66 + c] =
                        make_float2(acc[s][0] + gx0 * p0a + gy0 * p1a + pba,
                                    acc[s][1] + gx0 * p0b + gy0 * p1b + pbb);
                    *(float2*)&sTf[r1 * 66 + c] =
                        make_float2(acc[s][2] + gx1 * p0a + gy1 * p1a + pba,
                                    acc[s][3] + gx1 * p0b + gy1 * p1b + pbb);
                }
            }
            __syncthreads();

            for (int rr = warp; rr < 64; rr += 8) {
                float x0 = sTf[rr * 66 + lane], x1 = sTf[rr * 66 + lane + 32];
                float s1 = x0 + x1, s2 = x0 * x0 + x1 * x1;
                #pragma unroll
                for (int o = 16; o; o >>= 1) {
                    s1 += __shfl_xor_sync(0xffffffffu, s1, o);
                    s2 += __shfl_xor_sync(0xffffffffu, s2, o);
                }
                float mu = s1 * 0.015625f;
                float var = s2 * 0.015625f - mu * mu;
                float rs = rsqrtf(var + LNEPS);
                sTb[rr * 72 + lane]      = __float2bfloat16((x0 - mu) * rs * speg[lane]      + speb[lane]);
                sTb[rr * 72 + lane + 32] = __float2bfloat16((x1 - mu) * rs * speg[lane + 32] + speb[lane + 32]);
            }
            __syncthreads();

            {
                float acc[8][4];
                #pragma unroll
                for (int s = 0; s < 8; s++)
                    #pragma unroll
                    for (int j = 0; j < 4; j++) acc[s][j] = 0.f;

                #pragma unroll
                for (int ks = 0; ks < 4; ks++) {
                    u32 a[4];
                    ldsm_x4(a, sbTb + ((mt * 16 + l15) * 72 + ks * 16 + lh * 8) * 2);
                    #pragma unroll
                    for (int s = 0; s < 8; s++) {
                        u32 b[2];
                        int nb = ng * 64 + s * 8;
                        ldsm_x2t(b, sbW1 + ((ks * 16 + l15) * 136 + nb) * 2);
                        mma_bf16(acc[s], a, b);
                    }
                }
                __syncthreads();   // Tf reads done before H overwrite (alias safety)
                int r0 = mt * 16 + lr, r1 = r0 + 8;
                #pragma unroll
                for (int s = 0; s < 8; s++) {
                    int c = ng * 64 + s * 8 + lc;
                    float ba = sb1[c], bb = sb1[c + 1];
                    *(u32*)&sHb[r0 * 136 + c] =
                        bf2u(fmaxf(acc[s][0] + ba, 0.f), fmaxf(acc[s][1] + bb, 0.f));
                    *(u32*)&sHb[r1 * 136 + c] =
                        bf2u(fmaxf(acc[s][2] + ba, 0.f), fmaxf(acc[s][3] + bb, 0.f));
                }
            }
            __syncthreads();

            {
                float acc[4][4];
                #pragma unroll
                for (int s = 0; s < 4; s++)
                    #pragma unroll
                    for (int j = 0; j < 4; j++) acc[s][j] = 0.f;

                #pragma unroll
                for (int ks = 0; ks < 8; ks++) {
                    u32 a[4];
                    ldsm_x4(a, sbHb + ((mt * 16 + l15) * 136 + ks * 16 + lh * 8) * 2);
                    #pragma unroll
                    for (int s = 0; s < 4; s++) {
                        u32 b[2];
                        int nb = ng * 32 + s * 8;
                        ldsm_x2t(b, sbW2 + ((ks * 16 + l15) * 72 + nb) * 2);
                        mma_bf16(acc[s], a, b);
                    }
                }
                int r0 = mt * 16 + lr, r1 = r0 + 8;
                #pragma unroll
                for (int s = 0; s < 4; s++) {
                    int c = ng * 32 + s * 8 + lc;
                    float ba = sb2v[c], bb = sb2v[c + 1];
                    outg[(size_t)(rowbase + r0) * 32 + (c >> 1)] =
                        bf2u(acc[s][0] + ba, acc[s][1] + bb);
                    outg[(size_t)(rowbase + r1) * 32 + (c >> 1)] =
                        bf2u(acc[s][2] + ba, acc[s][3] + bb);
                }
            }
            __syncthreads();
        }
    }
}

// ---------------------------------------------------------------------------
// initq: s = broadcast(slots); q = LN(s; ln_s) @ Wq  (one block per b)
// ---------------------------------------------------------------------------
__global__ __launch_bounds__(256) void initq_kernel(
    const float* __restrict__ slots,
    const float* __restrict__ lnsg, const float* __restrict__ lnsb,
    const float* __restrict__ Wq)
{
    __shared__ float ss[512], sln[512];
    int b = blockIdx.x, t = threadIdx.x, warp = t >> 5, lane = t & 31;
    for (int i = t; i < 512; i += 256) {
        float v = slots[i];
        g_s[b * 512 + i] = v;
        ss[i] = v;
    }
    __syncthreads();
    {
        const float* row = ss + warp * 64;
        float x0 = row[lane], x1 = row[lane + 32];
        float s1 = x0 + x1, s2 = x0 * x0 + x1 * x1;
        #pragma unroll
        for (int o = 16; o; o >>= 1) {
            s1 += __shfl_xor_sync(0xffffffffu, s1, o);
            s2 += __shfl_xor_sync(0xffffffffu, s2, o);
        }
        float mu = s1 * 0.015625f;
        float var = s2 * 0.015625f - mu * mu;
        float rs = rsqrtf(var + LNEPS);
        sln[warp * 64 + lane]      = (x0 - mu) * rs * lnsg[lane]      + lnsb[lane];
        sln[warp * 64 + lane + 32] = (x1 - mu) * rs * lnsg[lane + 32] + lnsb[lane + 32];
    }
    __syncthreads();
    for (int i = t; i < 512; i += 256) {
        int s = i >> 6, c = i & 63;
        float a = 0.f;
        #pragma unroll 8
        for (int d = 0; d < 64; d++) a += sln[s * 64 + d] * Wq[d * 64 + c];
        g_q[b * 512 + i] = a;
    }
}

// ---------------------------------------------------------------------------
// Attention: HMMA logits AND HMMA a^T.v accumulation. 2 row-tiles/warp.
// Per tile: k -> smem, v -> regs; logits mma; softmax -> bf16 P smem;
// v regs -> smem (k region reused); D += V^T @ P via mma (trans A frags).
// smem: qTb bf16[64][8] @0 (1024) | sKu u32 per-warp [32][36] @1024 (36864) |
//       pawb bf16 per-warp [32][8] @37888 (4096) | wacc [8][520] @41984 (16640)
//       -> 58624 B (3 CTAs/SM)
// ---------------------------------------------------------------------------
#define ATTN_SMEM_BYTES 58624

__global__ __launch_bounds__(256, 3) void attn_kernel()
{
    extern __shared__ char smc[];
    __nv_bfloat16* qTb = (__nv_bfloat16*)smc;     // [64][8]
    float* wacc = (float*)(smc + 41984);          // [8][520]

    u32 sb = (u32)__cvta_generic_to_shared(smc);
    const u32 sbQ = sb, sbK = sb + 1024, sbP = sb + 37888;

    int b = blockIdx.x >> 5, pb = blockIdx.x & 31;
    int t = threadIdx.x, warp = t >> 5, lane = t & 31;
    const int l15 = lane & 15, lh = lane >> 4;
    const int q = lane >> 2, c0 = (lane & 3) * 2;
    const int lr = lane >> 2, lc = (lane & 3) * 2;

    for (int i = t; i < 512; i += 256) {
        int s = i >> 6, d = i & 63;
        qTb[d * 8 + s] = __float2bfloat16(g_q[b * 512 + i]);
    }
    __syncthreads();

    u32 qf[4][2];
    #pragma unroll
    for (int kc = 0; kc < 4; kc++)
        ldsm_x2t(qf[kc], sbQ + ((kc * 16 + l15) * 8) * 2);

    u32* mk = (u32*)(smc + 1024) + warp * 1152;
    const u32 wbase = sbK + warp * 4608;
    const u32 pbase = sbP + warp * 512;
    u32* pw = (u32*)(smc + 37888) + warp * 128;   // pawb as u32[32*4]

    // trans-A ldsm addressing for V^T frags:
    //   krow(lane) = (lane&7) + ((lane>>4)&1)*8   (within 16-row chunk)
    //   dcol(lane) = ((lane>>3)&1)*8              (within 16-col m-tile)
    const int tkrow = (lane & 7) + ((lane >> 4) & 1) * 8;
    const int tdcol = ((lane >> 3) & 1) * 8;

    // D accumulators: 4 m-tiles (d dim), each 2 rows x 2 slot-cols
    float df[4][4];
    #pragma unroll
    for (int m = 0; m < 4; m++)
        #pragma unroll
        for (int j = 0; j < 4; j++) df[m][j] = 0.f;
    float den0 = 0.f, den1 = 0.f;

    #pragma unroll 1
    for (int tt = 0; tt < 2; tt++) {
        size_t rowbase = (size_t)b * N_ + pb * 512 + tt * 256 + warp * 32;
        const unsigned* kp = g_kh + rowbase * 32;
        const unsigned* vp = g_vh + rowbase * 32;

        __syncwarp();   // prior tile's mk/pw reads complete before reuse
        #pragma unroll
        for (int i = 0; i < 32; i++) mk[i * 36 + lane] = kp[i * 32 + lane];
        u32 vreg[32];
        #pragma unroll
        for (int i = 0; i < 32; i++) vreg[i] = vp[i * 32 + lane];
        __syncwarp();

        // logits via HMMA: L[32x8] = K[32x64] @ Q^T
        float acc[2][4];
        #pragma unroll
        for (int m = 0; m < 2; m++)
            #pragma unroll
            for (int j = 0; j < 4; j++) acc[m][j] = 0.f;
        #pragma unroll
        for (int m = 0; m < 2; m++) {
            #pragma unroll
            for (int kc = 0; kc < 4; kc++) {
                u32 a[4];
                ldsm_x4(a, wbase + ((m * 16 + l15) * 72 + kc * 16 + lh * 8) * 2);
                mma_bf16(acc[m], a, qf[kc]);
            }
        }

        // softmax over S=8 per row -> bf16 P in smem; den from ROUNDED values
        #pragma unroll
        for (int m = 0; m < 2; m++) {
            #pragma unroll
            for (int h = 0; h < 2; h++) {
                float e0 = acc[m][h * 2]     * 0.125f;
                float e1 = acc[m][h * 2 + 1] * 0.125f;
                float mx = fmaxf(e0, e1);
                mx = fmaxf(mx, __shfl_xor_sync(0xffffffffu, mx, 1));
                mx = fmaxf(mx, __shfl_xor_sync(0xffffffffu, mx, 2));
                e0 = __expf(e0 - mx); e1 = __expf(e1 - mx);
                float se = e0 + e1;
                se += __shfl_xor_sync(0xffffffffu, se, 1);
                se += __shfl_xor_sync(0xffffffffu, se, 2);
                float inv = 1.f / se;
                e0 = e0 * inv + ATTN_EPS;
                e1 = e1 * inv + ATTN_EPS;
                unsigned pk = bf2u(e0, e1);
                int row = m * 16 + h * 8 + q;
                pw[row * 4 + (lane & 3)] = pk;
                float2 rr2 = u2f2(pk);        // rounded values for den consistency
                den0 += rr2.x; den1 += rr2.y;
            }
        }
        __syncwarp();

        // v regs -> smem (k region dead after logits)
        #pragma unroll
        for (int i = 0; i < 32; i++) mk[i * 36 + lane] = vreg[i];
        __syncwarp();

        // D += V^T(64x32) @ P(32x8): 4 m-tiles x 2 k-chunks
        #pragma unroll
        for (int kc = 0; kc < 2; kc++) {
            u32 bfr[2];
            ldsm_x2t(bfr, pbase + ((kc * 16 + l15) * 8) * 2);
            #pragma unroll
            for (int m = 0; m < 4; m++) {
                u32 a[4];
                ldsm_x4t(a, wbase + ((kc * 16 + tkrow) * 72 + m * 16 + tdcol) * 2);
                mma_bf16(df[m], a, bfr);
            }
        }
    }

    // per-slot denominators: reduce over lanes with same (lane&3)
    den0 += __shfl_xor_sync(0xffffffffu, den0, 4);
    den0 += __shfl_xor_sync(0xffffffffu, den0, 8);
    den0 += __shfl_xor_sync(0xffffffffu, den0, 16);
    den1 += __shfl_xor_sync(0xffffffffu, den1, 4);
    den1 += __shfl_xor_sync(0xffffffffu, den1, 8);
    den1 += __shfl_xor_sync(0xffffffffu, den1, 16);

    float* wa = wacc + warp * 520;
    // df[m]: rows d = m*16+lr, m*16+lr+8 ; cols slots lc, lc+1
    #pragma unroll
    for (int m = 0; m < 4; m++) {
        int d0 = m * 16 + lr, d1 = d0 + 8;
        wa[lc * 64 + d0]       = df[m][0];
        wa[(lc + 1) * 64 + d0] = df[m][1];
        wa[lc * 64 + d1]       = df[m][2];
        wa[(lc + 1) * 64 + d1] = df[m][3];
    }
    if (lane < 4) {
        wa[512 + c0]     = den0;
        wa[512 + c0 + 1] = den1;
    }
    __syncthreads();

    float* dst = g_part + (size_t)blockIdx.x * 520;
    for (int i = t; i < 520; i += 256) {
        float v = 0.f;
        #pragma unroll
        for (int w = 0; w < 8; w++) v += wacc[w * 520 + i];
        dst[i] = v;
    }
}

// ---------------------------------------------------------------------------
// update: one block per (b, slot); L2 warm-up prefetch of all weights, then
// 4-way parallel partial reduction and the serial GRU/MLP/q chain.
// ---------------------------------------------------------------------------
__global__ __launch_bounds__(256) void update_kernel(
    const float* __restrict__ W_ih, const float* __restrict__ W_hh,
    const float* __restrict__ b_ih, const float* __restrict__ b_hh,
    const float* __restrict__ lnmg, const float* __restrict__ lnmb,
    const float* __restrict__ mW1,  const float* __restrict__ mb1,
    const float* __restrict__ mW2,  const float* __restrict__ mb2,
    const float* __restrict__ lnsg, const float* __restrict__ lnsb,
    const float* __restrict__ Wq,
    float* __restrict__ dout)
{
    __shared__ float sRed[4][64], sDen[4], sSink;
    __shared__ float u[64], prev[64], gx[192], gh[192];
    __shared__ float snew[64], sln[64], h1[128];
    int b = blockIdx.x >> 3, s = blockIdx.x & 7;
    int t = threadIdx.x, warp = t >> 5, lane = t & 31;
    int g = t >> 6, e = t & 63;

    // ---- L2 warm-up: touch one float per 128B line of every weight matrix,
    // high MLP, overlapped with the partial reduction below ----
    float sink = 0.f;
    {
        for (int l = t; l < 384; l += 256) { sink += W_ih[l * 32]; sink += W_hh[l * 32]; }
        sink += mW1[t * 32];
        sink += mW2[t * 32];
        if (t < 128) sink += Wq[t * 32];
    }

    // ---- parallel reduction: group g sums partial blocks [8g, 8g+8) ----
    {
        const float* p = g_part + (size_t)(b * 32) * 520 + (size_t)g * 8 * 520;
        float v = 0.f;
        #pragma unroll
        for (int j = 0; j < 8; j++) v += p[j * 520 + s * 64 + e];
        sRed[g][e] = v;
        if (t < 4) {
            const float* pd = g_part + (size_t)(b * 32) * 520 + (size_t)t * 8 * 520;
            float dv = 0.f;
            #pragma unroll
            for (int j = 0; j < 8; j++) dv += pd[j * 520 + 512 + s];
            sDen[t] = dv;
        }
        if (t >= 64 && t < 128) prev[e] = g_s[b * 512 + s * 64 + e];
    }
    if (sink == -12345.678f) sSink = sink;   // keep prefetch live
    __syncthreads();

    if (t < 64) {
        float den = sDen[0] + sDen[1] + sDen[2] + sDen[3];
        u[t] = (sRed[0][t] + sRed[1][t] + sRed[2][t] + sRed[3][t]) / den;
    }
    __syncthreads();

    if (t < 192) {
        float ax = b_ih[t], ah = b_hh[t];
        #pragma unroll 8
        for (int d = 0; d < 64; d++) {
            ax += u[d]    * W_ih[d * 192 + t];
            ah += prev[d] * W_hh[d * 192 + t];
        }
        gx[t] = ax; gh[t] = ah;
    }
    __syncthreads();

    if (t < 64) {
        float xr = gx[t], xz = gx[64 + t], xn = gx[128 + t];
        float hr = gh[t], hz = gh[64 + t], hn = gh[128 + t];
        float r_ = 1.f / (1.f + __expf(-(xr + hr)));
        float z  = 1.f / (1.f + __expf(-(xz + hz)));
        float nn = tanhf(xn + r_ * hn);
        snew[t] = (1.f - z) * nn + z * prev[t];
    }
    __syncthreads();

    if (warp == 0) {
        float x0 = snew[lane], x1 = snew[lane + 32];
        float s1 = x0 + x1, s2 = x0 * x0 + x1 * x1;
        #pragma unroll
        for (int o = 16; o; o >>= 1) {
            s1 += __shfl_xor_sync(0xffffffffu, s1, o);
            s2 += __shfl_xor_sync(0xffffffffu, s2, o);
        }
        float mu = s1 * 0.015625f;
        float var = s2 * 0.015625f - mu * mu;
        float rs = rsqrtf(var + LNEPS);
        sln[lane]      = (x0 - mu) * rs * lnmg[lane]      + lnmb[lane];
        sln[lane + 32] = (x1 - mu) * rs * lnmg[lane + 32] + lnmb[lane + 32];
    }
    __syncthreads();

    if (t < 128) {
        float a = mb1[t];
        #pragma unroll 8
        for (int d = 0; d < 64; d++) a += sln[d] * mW1[d * 128 + t];
        h1[t] = fmaxf(a, 0.f);
    }
    __syncthreads();

    if (t < 64) {
        float a = mb2[t];
        #pragma unroll 8
        for (int k = 0; k < 128; k++) a += h1[k] * mW2[k * 64 + t];
        float val = snew[t] + a;
        g_s[b * 512 + s * 64 + t] = val;
        dout[b * 512 + s * 64 + t] = val;
        u[t] = val;   // reuse for next-q LN
    }
    __syncthreads();

    if (warp == 0) {
        float x0 = u[lane], x1 = u[lane + 32];
        float s1 = x0 + x1, s2 = x0 * x0 + x1 * x1;
        #pragma unroll
        for (int o = 16; o; o >>= 1) {
            s1 += __shfl_xor_sync(0xffffffffu, s1, o);
            s2 += __shfl_xor_sync(0xffffffffu, s2, o);
        }
        float mu = s1 * 0.015625f;
        float var = s2 * 0.015625f - mu * mu;
        float rs = rsqrtf(var + LNEPS);
        sln[lane]      = (x0 - mu) * rs * lnsg[lane]      + lnsb[lane];
        sln[lane + 32] = (x1 - mu) * rs * lnsg[lane + 32] + lnsb[lane + 32];
    }
    __syncthreads();
    if (t < 64) {
        float a = 0.f;
        #pragma unroll 8
        for (int d = 0; d < 64; d++) a += sln[d] * Wq[d * 64 + t];
        g_q[b * 512 + s * 64 + t] = a;
    }
}

// ---------------------------------------------------------------------------
extern "C" void kernel_launch(void* const* d_in, const int* in_sizes, int n_in,
                              void* d_out, int out_size)
{
    (void)in_sizes; (void)n_in; (void)out_size;
    const float* inputs  = (const float*)d_in[0];
    const float* slots   = (const float*)d_in[1];
    const float* ln_in_g = (const float*)d_in[2];
    const float* ln_in_b = (const float*)d_in[3];
    const float* ln_s_g  = (const float*)d_in[4];
    const float* ln_s_b  = (const float*)d_in[5];
    const float* ln_m_g  = (const float*)d_in[6];
    const float* ln_m_b  = (const float*)d_in[7];
    const float* Wq      = (const float*)d_in[8];
    const float* Wk      = (const float*)d_in[9];
    const float* Wv      = (const float*)d_in[10];
    const float* W_ih    = (const float*)d_in[11];
    const float* W_hh    = (const float*)d_in[12];
    const float* b_ih    = (const float*)d_in[13];
    const float* b_hh    = (const float*)d_in[14];
    const float* mlp_W1  = (const float*)d_in[15];
    const float* mlp_b1  = (const float*)d_in[16];
    const float* mlp_W2  = (const float*)d_in[17];
    const float* mlp_b2  = (const float*)d_in[18];
    const float* pa_W    = (const float*)d_in[19];
    const float* pa_b    = (const float*)d_in[20];
    const float* pe_g    = (const float*)d_in[21];
    const float* pe_b    = (const float*)d_in[22];
    const float* pe_W1   = (const float*)d_in[23];
    const float* pe_b1   = (const float*)d_in[24];
    const float* pe_W2   = (const float*)d_in[25];
    const float* pe_b2   = (const float*)d_in[26];
    float* out = (float*)d_out;

    static int configured = 0;
    if (!configured) {
        cudaFuncSetAttribute(preprocess_kernel,
                             cudaFuncAttributeMaxDynamicSharedMemorySize, PRE_SMEM_BYTES);
        cudaFuncSetAttribute(attn_kernel,
                             cudaFuncAttributeMaxDynamicSharedMemorySize, ATTN_SMEM_BYTES);
        configured = 1;
    }

    preprocess_kernel<<<2048, 256, PRE_SMEM_BYTES>>>(
        inputs, ln_in_g, ln_in_b, Wk, Wv, pa_W, pa_b, pe_g, pe_b,
        pe_W1, pe_b1, pe_W2, pe_b2);

    initq_kernel<<<32, 256>>>(slots, ln_s_g, ln_s_b, Wq);

    for (int it = 0; it < 3; it++) {
        attn_kernel<<<1024, 256, ATTN_SMEM_BYTES>>>();
        update_kernel<<<256, 256>>>(W_ih, W_hh, b_ih, b_hh,
                                    ln_m_g, ln_m_b,
                                    mlp_W1, mlp_b1, mlp_W2, mlp_b2,
                                    ln_s_g, ln_s_b, Wq, out);
    }
}

// round 17
// speedup vs baseline: 1.3501x; 1.1773x over previous
#include <cuda_runtime.h>
#include <cuda_bf16.h>
#include <cmath>

#define B_ 32
#define N_ 16384
#define D_ 64
#define S_ 8
#define H_ 128
#define LNEPS 1e-5f
#define ATTN_EPS 1e-8f

typedef unsigned long long ull;
typedef unsigned int u32;

// ---------------- scratch (device globals; no allocations allowed) ----------
__device__ unsigned g_kh[B_ * N_ * 32];   // k_pos bf16x2 (64 MB)
__device__ unsigned g_vh[B_ * N_ * 32];   // v_pos bf16x2 (64 MB)
__device__ float g_q[B_ * S_ * D_];
__device__ float g_s[B_ * S_ * D_];
__device__ float g_part[B_ * 32 * 520];   // per-(b, partial-block) numer(512)+den(8)

// ---------------- helpers ----------------------------------------------------
__device__ __forceinline__ unsigned bf2u(float a, float b) {
    __nv_bfloat162 h = __float22bfloat162_rn(make_float2(a, b));
    return *(unsigned*)&h;
}
__device__ __forceinline__ float2 u2f2(unsigned u) {
    __nv_bfloat162 h = *(__nv_bfloat162*)&u;
    return __bfloat1622float2(h);
}
__device__ __forceinline__ void ldsm_x4(u32 a[4], u32 addr) {
    asm volatile("ldmatrix.sync.aligned.m8n8.x4.shared.b16 {%0,%1,%2,%3}, [%4];"
                 : "=r"(a[0]), "=r"(a[1]), "=r"(a[2]), "=r"(a[3]) : "r"(addr));
}
__device__ __forceinline__ void ldsm_x4t(u32 a[4], u32 addr) {
    asm volatile("ldmatrix.sync.aligned.m8n8.x4.trans.shared.b16 {%0,%1,%2,%3}, [%4];"
                 : "=r"(a[0]), "=r"(a[1]), "=r"(a[2]), "=r"(a[3]) : "r"(addr));
}
__device__ __forceinline__ void ldsm_x2t(u32 b[2], u32 addr) {
    asm volatile("ldmatrix.sync.aligned.m8n8.x2.trans.shared.b16 {%0,%1}, [%2];"
                 : "=r"(b[0]), "=r"(b[1]) : "r"(addr));
}
__device__ __forceinline__ void mma_bf16(float d[4], const u32 a[4], const u32 b[2]) {
    asm volatile("mma.sync.aligned.m16n8k16.row.col.f32.bf16.bf16.f32 "
                 "{%0,%1,%2,%3},{%4,%5,%6,%7},{%8,%9},{%0,%1,%2,%3};"
                 : "+f"(d[0]), "+f"(d[1]), "+f"(d[2]), "+f"(d[3])
                 : "r"(a[0]), "r"(a[1]), "r"(a[2]), "r"(a[3]), "r"(b[0]), "r"(b[1]));
}

// ---------------------------------------------------------------------------
// Kernel 1: fused preprocessing with SHUFFLE-FREE LN.
// smem layout (bytes):
//   sWk 0 (9216) | sWv 9216 (9216) | sW1 18432 (17408) | sW2 35840 (18432) |
//   sX 54272 (9216) | sTf/sIn/sHb 63488 (17408) | sTb 80896 (9216) |
//   sV 90112 (2560) | sG 92672 (512) | sMu 93184 (256) | sRs 93440 (256)
//   -> 93696 B (2 CTAs/SM)
// ---------------------------------------------------------------------------
#define PRE_SMEM_BYTES 93696

__global__ __launch_bounds__(256, 2) void preprocess_kernel(
    const float* __restrict__ inp,
    const float* __restrict__ lng, const float* __restrict__ lnb,
    const float* __restrict__ Wk,  const float* __restrict__ Wv,
    const float* __restrict__ paW, const float* __restrict__ pab,
    const float* __restrict__ peg, const float* __restrict__ peb,
    const float* __restrict__ W1,  const float* __restrict__ b1,
    const float* __restrict__ W2,  const float* __restrict__ b2)
{
    extern __shared__ char smem[];
    __nv_bfloat16* sWk = (__nv_bfloat16*)(smem);
    __nv_bfloat16* sWv = (__nv_bfloat16*)(smem + 9216);
    __nv_bfloat16* sW1 = (__nv_bfloat16*)(smem + 18432);
    __nv_bfloat16* sW2 = (__nv_bfloat16*)(smem + 35840);
    __nv_bfloat16* sX  = (__nv_bfloat16*)(smem + 54272);
    float*         sTf = (float*)(smem + 63488);          // aliased: sIn / sHb
    __nv_bfloat16* sHb = (__nv_bfloat16*)(smem + 63488);
    __nv_bfloat16* sTb = (__nv_bfloat16*)(smem + 80896);
    float*         sV  = (float*)(smem + 90112);
    float*         sG  = (float*)(smem + 92672);
    float*         sMu = (float*)(smem + 93184);
    float*         sRs = (float*)(smem + 93440);

    u32 sb = (u32)__cvta_generic_to_shared(smem);
    const u32 sbWk = sb, sbWv = sb + 9216, sbW1 = sb + 18432, sbW2 = sb + 35840;
    const u32 sbX = sb + 54272, sbHb = sb + 63488, sbTb = sb + 80896;

    const int t = threadIdx.x, warp = t >> 5, lane = t & 31;
    const int mt = warp >> 1, ng = warp & 1;
    const int l15 = lane & 15, lh = lane >> 4, lr = lane >> 2, lc = (lane & 3) * 2;
    const int srow = t >> 2, sq = t & 3;   // stats: 4 threads per row

    for (int i = t; i < 4096; i += 256) {
        int r = i >> 6, c = i & 63;
        sWk[r * 72 + c] = __float2bfloat16(Wk[i]);
        sWv[r * 72 + c] = __float2bfloat16(Wv[i]);
    }
    for (int i = t; i < 8192; i += 256) {
        int r1_ = i >> 7, c1_ = i & 127;
        sW1[r1_ * 136 + c1_] = __float2bfloat16(W1[i]);
        int r2_ = i >> 6, c2_ = i & 63;
        sW2[r2_ * 72 + c2_] = __float2bfloat16(W2[i]);
    }
    if (t < 64) {
        sV[t]       = paW[t];
        sV[64 + t]  = paW[64 + t];
        sV[128 + t] = pab[t];
        sV[192 + t] = lng[t];
        sV[256 + t] = lnb[t];
        sV[320 + t] = peg[t];
        sV[384 + t] = peb[t];
        sV[576 + t] = b2[t];
    }
    if (t < 128) sV[448 + t] = b1[t];
    __syncthreads();

    const float *pa0 = sV, *pa1 = sV + 64, *pbv = sV + 128,
                *sing = sV + 192, *sinb = sV + 256,
                *speg = sV + 320, *speb = sV + 384,
                *sb1 = sV + 448, *sb2v = sV + 576;

    for (int ti = 0; ti < 4; ti++) {
        int tile = blockIdx.x * 4 + ti;          // 8192 tiles of 64 rows
        int rowbase = tile * 64;

        // ---- stage input tile (64 x 66 floats) coalesced into sTf/sIn ----
        {
            const float4* in4 = (const float4*)(inp + (size_t)rowbase * 66);
            float4* s4 = (float4*)sTf;
            #pragma unroll
            for (int i = 0; i < 4; i++) s4[t + i * 256] = in4[t + i * 256];
            if (t < 32) s4[t + 1024] = in4[t + 1024];
        }
        __syncthreads();

        // ---- stats1: 4 threads/row, depth-2 shuffle; + grids extraction ----
        {
            const float* p = sTf + srow * 66 + sq * 16;
            float s1 = 0.f, s2 = 0.f;
            #pragma unroll
            for (int j = 0; j < 8; j++) {
                float2 x = *(const float2*)(p + 2 * j);
                s1 += x.x + x.y; s2 += x.x * x.x + x.y * x.y;
            }
            s1 += __shfl_xor_sync(0xffffffffu, s1, 1);
            s2 += __shfl_xor_sync(0xffffffffu, s2, 1);
            s1 += __shfl_xor_sync(0xffffffffu, s1, 2);
            s2 += __shfl_xor_sync(0xffffffffu, s2, 2);
            if (sq == 0) {
                float mu = s1 * 0.015625f;
                float var = s2 * 0.015625f - mu * mu;
                sMu[srow] = mu; sRs[srow] = rsqrtf(var + LNEPS);
            }
            if (t < 128) sG[t] = sTf[(t >> 1) * 66 + 64 + (t & 1)];
        }
        __syncthreads();

        // ---- normalize1 -> bf16 sX (no shuffles) ----
        for (int rr = warp; rr < 64; rr += 8) {
            float mu = sMu[rr], rs = sRs[rr];
            float x0 = sTf[rr * 66 + lane], x1 = sTf[rr * 66 + lane + 32];
            sX[rr * 72 + lane]      = __float2bfloat16((x0 - mu) * rs * sing[lane]      + sinb[lane]);
            sX[rr * 72 + lane + 32] = __float2bfloat16((x1 - mu) * rs * sing[lane + 32] + sinb[lane + 32]);
        }
        __syncthreads();

        #pragma unroll 1
        for (int pass = 0; pass < 2; pass++) {
            const u32 sbW = pass ? sbWv : sbWk;
            unsigned* outg = pass ? g_vh : g_kh;

            // ---- GEMM1 (tensor): Tf = X@W + gridproj ----
            {
                float acc[4][4];
                #pragma unroll
                for (int s = 0; s < 4; s++)
                    #pragma unroll
                    for (int j = 0; j < 4; j++) acc[s][j] = 0.f;

                #pragma unroll
                for (int ks = 0; ks < 4; ks++) {
                    u32 a[4];
                    ldsm_x4(a, sbX + ((mt * 16 + l15) * 72 + ks * 16 + lh * 8) * 2);
                    #pragma unroll
                    for (int s = 0; s < 4; s++) {
                        u32 b[2];
                        int nb = ng * 32 + s * 8;
                        ldsm_x2t(b, sbW + ((ks * 16 + l15) * 72 + nb) * 2);
                        mma_bf16(acc[s], a, b);
                    }
                }
                int r0 = mt * 16 + lr, r1 = r0 + 8;
                float gx0 = sG[r0 * 2], gy0 = sG[r0 * 2 + 1];
                float gx1 = sG[r1 * 2], gy1 = sG[r1 * 2 + 1];
                #pragma unroll
                for (int s = 0; s < 4; s++) {
                    int c = ng * 32 + s * 8 + lc;
                    float p0a = pa0[c], p0b = pa0[c + 1];
                    float p1a = pa1[c], p1b = pa1[c + 1];
                    float pba = pbv[c], pbb = pbv[c + 1];
                    *(float2*)&sTf[r0 * 66 + c] =
                        make_float2(acc[s][0] + gx0 * p0a + gy0 * p1a + pba,
                                    acc[s][1] + gx0 * p0b + gy0 * p1b + pbb);
                    *(float2*)&sTf[r1 * 66 + c] =
                        make_float2(acc[s][2] + gx1 * p0a + gy1 * p1a + pba,
                                    acc[s][3] + gx1 * p0b + gy1 * p1b + pbb);
                }
            }
            __syncthreads();

            // ---- stats2: 4 threads/row, depth-2 shuffle ----
            {
                const float* p = sTf + srow * 66 + sq * 16;
                float s1 = 0.f, s2 = 0.f;
                #pragma unroll
                for (int j = 0; j < 8; j++) {
                    float2 x = *(const float2*)(p + 2 * j);
                    s1 += x.x + x.y; s2 += x.x * x.x + x.y * x.y;
                }
                s1 += __shfl_xor_sync(0xffffffffu, s1, 1);
                s2 += __shfl_xor_sync(0xffffffffu, s2, 1);
                s1 += __shfl_xor_sync(0xffffffffu, s1, 2);
                s2 += __shfl_xor_sync(0xffffffffu, s2, 2);
                if (sq == 0) {
                    float mu = s1 * 0.015625f;
                    float var = s2 * 0.015625f - mu * mu;
                    sMu[srow] = mu; sRs[srow] = rsqrtf(var + LNEPS);
                }
            }
            __syncthreads();

            // ---- normalize2 (pe LN) -> bf16 sTb (no shuffles) ----
            for (int rr = warp; rr < 64; rr += 8) {
                float mu = sMu[rr], rs = sRs[rr];
                float x0 = sTf[rr * 66 + lane], x1 = sTf[rr * 66 + lane + 32];
                sTb[rr * 72 + lane]      = __float2bfloat16((x0 - mu) * rs * speg[lane]      + speb[lane]);
                sTb[rr * 72 + lane + 32] = __float2bfloat16((x1 - mu) * rs * speg[lane + 32] + speb[lane + 32]);
            }
            __syncthreads();   // sTb ready; sTf now dead (safe for sHb overwrite)

            // ---- GEMM2 (tensor): H = relu(Tb @ W1 + b1) -> bf16 sHb ----
            {
                float acc[8][4];
                #pragma unroll
                for (int s = 0; s < 8; s++)
                    #pragma unroll
                    for (int j = 0; j < 4; j++) acc[s][j] = 0.f;

                #pragma unroll
                for (int ks = 0; ks < 4; ks++) {
                    u32 a[4];
                    ldsm_x4(a, sbTb + ((mt * 16 + l15) * 72 + ks * 16 + lh * 8) * 2);
                    #pragma unroll
                    for (int s = 0; s < 8; s++) {
                        u32 b[2];
                        int nb = ng * 64 + s * 8;
                        ldsm_x2t(b, sbW1 + ((ks * 16 + l15) * 136 + nb) * 2);
                        mma_bf16(acc[s], a, b);
                    }
                }
                int r0 = mt * 16 + lr, r1 = r0 + 8;
                #pragma unroll
                for (int s = 0; s < 8; s++) {
                    int c = ng * 64 + s * 8 + lc;
                    float ba = sb1[c], bb = sb1[c + 1];
                    *(u32*)&sHb[r0 * 136 + c] =
                        bf2u(fmaxf(acc[s][0] + ba, 0.f), fmaxf(acc[s][1] + bb, 0.f));
                    *(u32*)&sHb[r1 * 136 + c] =
                        bf2u(fmaxf(acc[s][2] + ba, 0.f), fmaxf(acc[s][3] + bb, 0.f));
                }
            }
            __syncthreads();

            // ---- GEMM3 (tensor): out = H @ W2 + b2 -> bf16x2 gmem ----
            {
                float acc[4][4];
                #pragma unroll
                for (int s = 0; s < 4; s++)
                    #pragma unroll
                    for (int j = 0; j < 4; j++) acc[s][j] = 0.f;

                #pragma unroll
                for (int ks = 0; ks < 8; ks++) {
                    u32 a[4];
                    ldsm_x4(a, sbHb + ((mt * 16 + l15) * 136 + ks * 16 + lh * 8) * 2);
                    #pragma unroll
                    for (int s = 0; s < 4; s++) {
                        u32 b[2];
                        int nb = ng * 32 + s * 8;
                        ldsm_x2t(b, sbW2 + ((ks * 16 + l15) * 72 + nb) * 2);
                        mma_bf16(acc[s], a, b);
                    }
                }
                int r0 = mt * 16 + lr, r1 = r0 + 8;
                #pragma unroll
                for (int s = 0; s < 4; s++) {
                    int c = ng * 32 + s * 8 + lc;
                    float ba = sb2v[c], bb = sb2v[c + 1];
                    outg[(size_t)(rowbase + r0) * 32 + (c >> 1)] =
                        bf2u(acc[s][0] + ba, acc[s][1] + bb);
                    outg[(size_t)(rowbase + r1) * 32 + (c >> 1)] =
                        bf2u(acc[s][2] + ba, acc[s][3] + bb);
                }
            }
            __syncthreads();   // sHb dead before next GEMM1/copy writes sTf
        }
    }
}

// ---------------------------------------------------------------------------
// initq: s = broadcast(slots); q = LN(s; ln_s) @ Wq  (one block per b)
// ---------------------------------------------------------------------------
__global__ __launch_bounds__(256) void initq_kernel(
    const float* __restrict__ slots,
    const float* __restrict__ lnsg, const float* __restrict__ lnsb,
    const float* __restrict__ Wq)
{
    __shared__ float ss[512], sln[512];
    int b = blockIdx.x, t = threadIdx.x, warp = t >> 5, lane = t & 31;
    for (int i = t; i < 512; i += 256) {
        float v = slots[i];
        g_s[b * 512 + i] = v;
        ss[i] = v;
    }
    __syncthreads();
    {
        const float* row = ss + warp * 64;
        float x0 = row[lane], x1 = row[lane + 32];
        float s1 = x0 + x1, s2 = x0 * x0 + x1 * x1;
        #pragma unroll
        for (int o = 16; o; o >>= 1) {
            s1 += __shfl_xor_sync(0xffffffffu, s1, o);
            s2 += __shfl_xor_sync(0xffffffffu, s2, o);
        }
        float mu = s1 * 0.015625f;
        float var = s2 * 0.015625f - mu * mu;
        float rs = rsqrtf(var + LNEPS);
        sln[warp * 64 + lane]      = (x0 - mu) * rs * lnsg[lane]      + lnsb[lane];
        sln[warp * 64 + lane + 32] = (x1 - mu) * rs * lnsg[lane + 32] + lnsb[lane + 32];
    }
    __syncthreads();
    for (int i = t; i < 512; i += 256) {
        int s = i >> 6, c = i & 63;
        float a = 0.f;
        #pragma unroll 8
        for (int d = 0; d < 64; d++) a += sln[s * 64 + d] * Wq[d * 64 + c];
        g_q[b * 512 + i] = a;
    }
}

// ---------------------------------------------------------------------------
// Attention (unchanged from R16): HMMA logits + HMMA a^T.v, 2 tiles/warp.
// ---------------------------------------------------------------------------
#define ATTN_SMEM_BYTES 58624

__global__ __launch_bounds__(256, 3) void attn_kernel()
{
    extern __shared__ char smc[];
    __nv_bfloat16* qTb = (__nv_bfloat16*)smc;     // [64][8]
    float* wacc = (float*)(smc + 41984);          // [8][520]

    u32 sb = (u32)__cvta_generic_to_shared(smc);
    const u32 sbQ = sb, sbK = sb + 1024, sbP = sb + 37888;

    int b = blockIdx.x >> 5, pb = blockIdx.x & 31;
    int t = threadIdx.x, warp = t >> 5, lane = t & 31;
    const int l15 = lane & 15, lh = lane >> 4;
    const int q = lane >> 2, c0 = (lane & 3) * 2;
    const int lr = lane >> 2, lc = (lane & 3) * 2;

    for (int i = t; i < 512; i += 256) {
        int s = i >> 6, d = i & 63;
        qTb[d * 8 + s] = __float2bfloat16(g_q[b * 512 + i]);
    }
    __syncthreads();

    u32 qf[4][2];
    #pragma unroll
    for (int kc = 0; kc < 4; kc++)
        ldsm_x2t(qf[kc], sbQ + ((kc * 16 + l15) * 8) * 2);

    u32* mk = (u32*)(smc + 1024) + warp * 1152;
    const u32 wbase = sbK + warp * 4608;
    const u32 pbase = sbP + warp * 512;
    u32* pw = (u32*)(smc + 37888) + warp * 128;

    const int tkrow = (lane & 7) + ((lane >> 4) & 1) * 8;
    const int tdcol = ((lane >> 3) & 1) * 8;

    float df[4][4];
    #pragma unroll
    for (int m = 0; m < 4; m++)
        #pragma unroll
        for (int j = 0; j < 4; j++) df[m][j] = 0.f;
    float den0 = 0.f, den1 = 0.f;

    #pragma unroll 1
    for (int tt = 0; tt < 2; tt++) {
        size_t rowbase = (size_t)b * N_ + pb * 512 + tt * 256 + warp * 32;
        const unsigned* kp = g_kh + rowbase * 32;
        const unsigned* vp = g_vh + rowbase * 32;

        __syncwarp();
        #pragma unroll
        for (int i = 0; i < 32; i++) mk[i * 36 + lane] = kp[i * 32 + lane];
        u32 vreg[32];
        #pragma unroll
        for (int i = 0; i < 32; i++) vreg[i] = vp[i * 32 + lane];
        __syncwarp();

        float acc[2][4];
        #pragma unroll
        for (int m = 0; m < 2; m++)
            #pragma unroll
            for (int j = 0; j < 4; j++) acc[m][j] = 0.f;
        #pragma unroll
        for (int m = 0; m < 2; m++) {
            #pragma unroll
            for (int kc = 0; kc < 4; kc++) {
                u32 a[4];
                ldsm_x4(a, wbase + ((m * 16 + l15) * 72 + kc * 16 + lh * 8) * 2);
                mma_bf16(acc[m], a, qf[kc]);
            }
        }

        #pragma unroll
        for (int m = 0; m < 2; m++) {
            #pragma unroll
            for (int h = 0; h < 2; h++) {
                float e0 = acc[m][h * 2]     * 0.125f;
                float e1 = acc[m][h * 2 + 1] * 0.125f;
                float mx = fmaxf(e0, e1);
                mx = fmaxf(mx, __shfl_xor_sync(0xffffffffu, mx, 1));
                mx = fmaxf(mx, __shfl_xor_sync(0xffffffffu, mx, 2));
                e0 = __expf(e0 - mx); e1 = __expf(e1 - mx);
                float se = e0 + e1;
                se += __shfl_xor_sync(0xffffffffu, se, 1);
                se += __shfl_xor_sync(0xffffffffu, se, 2);
                float inv = 1.f / se;
                e0 = e0 * inv + ATTN_EPS;
                e1 = e1 * inv + ATTN_EPS;
                unsigned pk = bf2u(e0, e1);
                int row = m * 16 + h * 8 + q;
                pw[row * 4 + (lane & 3)] = pk;
                float2 rr2 = u2f2(pk);
                den0 += rr2.x; den1 += rr2.y;
            }
        }
        __syncwarp();

        #pragma unroll
        for (int i = 0; i < 32; i++) mk[i * 36 + lane] = vreg[i];
        __syncwarp();

        #pragma unroll
        for (int kc = 0; kc < 2; kc++) {
            u32 bfr[2];
            ldsm_x2t(bfr, pbase + ((kc * 16 + l15) * 8) * 2);
            #pragma unroll
            for (int m = 0; m < 4; m++) {
                u32 a[4];
                ldsm_x4t(a, wbase + ((kc * 16 + tkrow) * 72 + m * 16 + tdcol) * 2);
                mma_bf16(df[m], a, bfr);
            }
        }
    }

    den0 += __shfl_xor_sync(0xffffffffu, den0, 4);
    den0 += __shfl_xor_sync(0xffffffffu, den0, 8);
    den0 += __shfl_xor_sync(0xffffffffu, den0, 16);
    den1 += __shfl_xor_sync(0xffffffffu, den1, 4);
    den1 += __shfl_xor_sync(0xffffffffu, den1, 8);
    den1 += __shfl_xor_sync(0xffffffffu, den1, 16);

    float* wa = wacc + warp * 520;
    #pragma unroll
    for (int m = 0; m < 4; m++) {
        int d0 = m * 16 + lr, d1 = d0 + 8;
        wa[lc * 64 + d0]       = df[m][0];
        wa[(lc + 1) * 64 + d0] = df[m][1];
        wa[lc * 64 + d1]       = df[m][2];
        wa[(lc + 1) * 64 + d1] = df[m][3];
    }
    if (lane < 4) {
        wa[512 + c0]     = den0;
        wa[512 + c0 + 1] = den1;
    }
    __syncthreads();

    float* dst = g_part + (size_t)blockIdx.x * 520;
    for (int i = t; i < 520; i += 256) {
        float v = 0.f;
        #pragma unroll
        for (int w = 0; w < 8; w++) v += wacc[w * 520 + i];
        dst[i] = v;
    }
}

// ---------------------------------------------------------------------------
// update: one block per (b, slot); 4-way parallel partial reduction.
// ---------------------------------------------------------------------------
__global__ __launch_bounds__(256) void update_kernel(
    const float* __restrict__ W_ih, const float* __restrict__ W_hh,
    const float* __restrict__ b_ih, const float* __restrict__ b_hh,
    const float* __restrict__ lnmg, const float* __restrict__ lnmb,
    const float* __restrict__ mW1,  const float* __restrict__ mb1,
    const float* __restrict__ mW2,  const float* __restrict__ mb2,
    const float* __restrict__ lnsg, const float* __restrict__ lnsb,
    const float* __restrict__ Wq,
    float* __restrict__ dout)
{
    __shared__ float sRed[4][64], sDen[4];
    __shared__ float u[64], prev[64], gx[192], gh[192];
    __shared__ float snew[64], sln[64], h1[128];
    int b = blockIdx.x >> 3, s = blockIdx.x & 7;
    int t = threadIdx.x, warp = t >> 5, lane = t & 31;
    int g = t >> 6, e = t & 63;

    {
        const float* p = g_part + (size_t)(b * 32) * 520 + (size_t)g * 8 * 520;
        float v = 0.f;
        #pragma unroll
        for (int j = 0; j < 8; j++) v += p[j * 520 + s * 64 + e];
        sRed[g][e] = v;
        if (t < 4) {
            const float* pd = g_part + (size_t)(b * 32) * 520 + (size_t)t * 8 * 520;
            float dv = 0.f;
            #pragma unroll
            for (int j = 0; j < 8; j++) dv += pd[j * 520 + 512 + s];
            sDen[t] = dv;
        }
        if (t >= 64 && t < 128) prev[e] = g_s[b * 512 + s * 64 + e];
    }
    __syncthreads();

    if (t < 64) {
        float den = sDen[0] + sDen[1] + sDen[2] + sDen[3];
        u[t] = (sRed[0][t] + sRed[1][t] + sRed[2][t] + sRed[3][t]) / den;
    }
    __syncthreads();

    if (t < 192) {
        float ax = b_ih[t], ah = b_hh[t];
        #pragma unroll 8
        for (int d = 0; d < 64; d++) {
            ax += u[d]    * W_ih[d * 192 + t];
            ah += prev[d] * W_hh[d * 192 + t];
        }
        gx[t] = ax; gh[t] = ah;
    }
    __syncthreads();

    if (t < 64) {
        float xr = gx[t], xz = gx[64 + t], xn = gx[128 + t];
        float hr = gh[t], hz = gh[64 + t], hn = gh[128 + t];
        float r_ = 1.f / (1.f + __expf(-(xr + hr)));
        float z  = 1.f / (1.f + __expf(-(xz + hz)));
        float nn = tanhf(xn + r_ * hn);
        snew[t] = (1.f - z) * nn + z * prev[t];
    }
    __syncthreads();

    if (warp == 0) {
        float x0 = snew[lane], x1 = snew[lane + 32];
        float s1 = x0 + x1, s2 = x0 * x0 + x1 * x1;
        #pragma unroll
        for (int o = 16; o; o >>= 1) {
            s1 += __shfl_xor_sync(0xffffffffu, s1, o);
            s2 += __shfl_xor_sync(0xffffffffu, s2, o);
        }
        float mu = s1 * 0.015625f;
        float var = s2 * 0.015625f - mu * mu;
        float rs = rsqrtf(var + LNEPS);
        sln[lane]      = (x0 - mu) * rs * lnmg[lane]      + lnmb[lane];
        sln[lane + 32] = (x1 - mu) * rs * lnmg[lane + 32] + lnmb[lane + 32];
    }
    __syncthreads();

    if (t < 128) {
        float a = mb1[t];
        #pragma unroll 8
        for (int d = 0; d < 64; d++) a += sln[d] * mW1[d * 128 + t];
        h1[t] = fmaxf(a, 0.f);
    }
    __syncthreads();

    if (t < 64) {
        float a = mb2[t];
        #pragma unroll 8
        for (int k = 0; k < 128; k++) a += h1[k] * mW2[k * 64 + t];
        float val = snew[t] + a;
        g_s[b * 512 + s * 64 + t] = val;
        dout[b * 512 + s * 64 + t] = val;
        u[t] = val;
    }
    __syncthreads();

    if (warp == 0) {
        float x0 = u[lane], x1 = u[lane + 32];
        float s1 = x0 + x1, s2 = x0 * x0 + x1 * x1;
        #pragma unroll
        for (int o = 16; o; o >>= 1) {
            s1 += __shfl_xor_sync(0xffffffffu, s1, o);
            s2 += __shfl_xor_sync(0xffffffffu, s2, o);
        }
        float mu = s1 * 0.015625f;
        float var = s2 * 0.015625f - mu * mu;
        float rs = rsqrtf(var + LNEPS);
        sln[lane]      = (x0 - mu) * rs * lnsg[lane]      + lnsb[lane];
        sln[lane + 32] = (x1 - mu) * rs * lnsg[lane + 32] + lnsb[lane + 32];
    }
    __syncthreads();
    if (t < 64) {
        float a = 0.f;
        #pragma unroll 8
        for (int d = 0; d < 64; d++) a += sln[d] * Wq[d * 64 + t];
        g_q[b * 512 + s * 64 + t] = a;
    }
}

// ---------------------------------------------------------------------------
extern "C" void kernel_launch(void* const* d_in, const int* in_sizes, int n_in,
                              void* d_out, int out_size)
{
    (void)in_sizes; (void)n_in; (void)out_size;
    const float* inputs  = (const float*)d_in[0];
    const float* slots   = (const float*)d_in[1];
    const float* ln_in_g = (const float*)d_in[2];
    const float* ln_in_b = (const float*)d_in[3];
    const float* ln_s_g  = (const float*)d_in[4];
    const float* ln_s_b  = (const float*)d_in[5];
    const float* ln_m_g  = (const float*)d_in[6];
    const float* ln_m_b  = (const float*)d_in[7];
    const float* Wq      = (const float*)d_in[8];
    const float* Wk      = (const float*)d_in[9];
    const float* Wv      = (const float*)d_in[10];
    const float* W_ih    = (const float*)d_in[11];
    const float* W_hh    = (const float*)d_in[12];
    const float* b_ih    = (const float*)d_in[13];
    const float* b_hh    = (const float*)d_in[14];
    const float* mlp_W1  = (const float*)d_in[15];
    const float* mlp_b1  = (const float*)d_in[16];
    const float* mlp_W2  = (const float*)d_in[17];
    const float* mlp_b2  = (const float*)d_in[18];
    const float* pa_W    = (const float*)d_in[19];
    const float* pa_b    = (const float*)d_in[20];
    const float* pe_g    = (const float*)d_in[21];
    const float* pe_b    = (const float*)d_in[22];
    const float* pe_W1   = (const float*)d_in[23];
    const float* pe_b1   = (const float*)d_in[24];
    const float* pe_W2   = (const float*)d_in[25];
    const float* pe_b2   = (const float*)d_in[26];
    float* out = (float*)d_out;

    static int configured = 0;
    if (!configured) {
        cudaFuncSetAttribute(preprocess_kernel,
                             cudaFuncAttributeMaxDynamicSharedMemorySize, PRE_SMEM_BYTES);
        cudaFuncSetAttribute(attn_kernel,
                             cudaFuncAttributeMaxDynamicSharedMemorySize, ATTN_SMEM_BYTES);
        configured = 1;
    }

    preprocess_kernel<<<2048, 256, PRE_SMEM_BYTES>>>(
        inputs, ln_in_g, ln_in_b, Wk, Wv, pa_W, pa_b, pe_g, pe_b,
        pe_W1, pe_b1, pe_W2, pe_b2);

    initq_kernel<<<32, 256>>>(slots, ln_s_g, ln_s_b, Wq);

    for (int it = 0; it < 3; it++) {
        attn_kernel<<<1024, 256, ATTN_SMEM_BYTES>>>();
        update_kernel<<<256, 256>>>(W_ih, W_hh, b_ih, b_hh,
                                    ln_m_g, ln_m_b,
                                    mlp_W1, mlp_b1, mlp_W2, mlp_b2,
                                    ln_s_g, ln_s_b, Wq, out);
    }
}